// round 8
// baseline (speedup 1.0000x reference)
#include <cuda_runtime.h>
#include <cuda_bf16.h>
#include <math.h>
#include <stdint.h>
#include <stddef.h>

#define BB 2
#define NN 2048
#define EE 256
#define HH 4
#define DKK 64
#define MTOT (BB*NN)

// 1/sqrt(64) * log2(e): scores produced in log2 domain for ex2-softmax
#define QSCALE 0.1803368801111204f

typedef unsigned int u32;
typedef unsigned long long u64;

__device__ __forceinline__ float ex2f(float x) {
    float r; asm("ex2.approx.f32 %0, %1;" : "=f"(r) : "f"(x)); return r;
}
__device__ __forceinline__ u32 sptr(const void* p) {
    return (u32)__cvta_generic_to_shared(p);
}
__device__ __forceinline__ void ldsm4(u32& r0, u32& r1, u32& r2, u32& r3, u32 a) {
    asm volatile("ldmatrix.sync.aligned.m8n8.x4.shared.b16 {%0,%1,%2,%3}, [%4];"
        : "=r"(r0), "=r"(r1), "=r"(r2), "=r"(r3) : "r"(a));
}
__device__ __forceinline__ void ldsm4t(u32& r0, u32& r1, u32& r2, u32& r3, u32 a) {
    asm volatile("ldmatrix.sync.aligned.m8n8.x4.trans.shared.b16 {%0,%1,%2,%3}, [%4];"
        : "=r"(r0), "=r"(r1), "=r"(r2), "=r"(r3) : "r"(a));
}
__device__ __forceinline__ void cpa16(u32 dst, const void* src) {
    asm volatile("cp.async.cg.shared.global [%0], [%1], 16;" :: "r"(dst), "l"(src));
}

// Scratch: everything the hot kernels touch is pre-split bf16 hi/lo.
__device__ __align__(16) __nv_bfloat16 g_Xh[MTOT*EE],  g_Xl[MTOT*EE];
__device__ __align__(16) __nv_bfloat16 g_Wh[12*DKK*EE], g_Wl[12*DKK*EE];
__device__ __align__(16) __nv_bfloat16 g_Woh[EE*EE],   g_Wol[EE*EE];
__device__ __align__(16) __nv_bfloat16 g_Qh[BB*HH*NN*DKK], g_Ql[BB*HH*NN*DKK];
__device__ __align__(16) __nv_bfloat16 g_Kh[BB*HH*NN*DKK], g_Kl[BB*HH*NN*DKK];
__device__ __align__(16) __nv_bfloat16 g_Vh[BB*HH*NN*DKK], g_Vl[BB*HH*NN*DKK];
__device__ __align__(16) __nv_bfloat16 g_Ch[MTOT*EE],  g_Cl[MTOT*EE];
__device__ u32 g_mask[BB*NN*NN/32];

// bf16 hi/lo split of a pair of floats
__device__ __forceinline__ void split2(float x, float y, u32& hi, u32& lo) {
    __nv_bfloat16 hx = __float2bfloat16(x), hy = __float2bfloat16(y);
    float rx = x - __bfloat162float(hx);
    float ry = y - __bfloat162float(hy);
    __nv_bfloat162 H = __halves2bfloat162(hx, hy);
    __nv_bfloat162 L = __halves2bfloat162(__float2bfloat16(rx), __float2bfloat16(ry));
    hi = *(u32*)&H; lo = *(u32*)&L;
}

#define MMA(d, a, b0_, b1_) asm volatile( \
    "mma.sync.aligned.m16n8k16.row.col.f32.bf16.bf16.f32 " \
    "{%0,%1,%2,%3}, {%4,%5,%6,%7}, {%8,%9}, {%0,%1,%2,%3};" \
    : "+f"(d[0]), "+f"(d[1]), "+f"(d[2]), "+f"(d[3]) \
    : "r"(a[0]), "r"(a[1]), "r"(a[2]), "r"(a[3]), "r"(b0_), "r"(b1_))

// ---------------------------------------------------------------------------
// Prep kernels (unchanged from R7).
// ---------------------------------------------------------------------------
__global__ void __launch_bounds__(256) mask_kernel(const int* __restrict__ Adj)
{
    int gid  = blockIdx.x * 256 + threadIdx.x;
    int word = gid >> 5, lane = gid & 31;
    int v = Adj[(size_t)word * 32 + lane];
    u32 m = __ballot_sync(0xffffffffu, v > 0);
    if (lane == 0) g_mask[word] = m;
}

__global__ void __launch_bounds__(256) xsplit_kernel(const float* __restrict__ X)
{
    int i = (blockIdx.x * 256 + threadIdx.x) * 4;
    float4 v = *(const float4*)&X[i];
    u32 h0, l0, h1, l1;
    split2(v.x, v.y, h0, l0);
    split2(v.z, v.w, h1, l1);
    *(u32*)&g_Xh[i]     = h0; *(u32*)&g_Xh[i + 2] = h1;
    *(u32*)&g_Xl[i]     = l0; *(u32*)&g_Xl[i + 2] = l1;
}

__global__ void __launch_bounds__(256) wsplit_kernel(
    const float* __restrict__ Wq, const float* __restrict__ Wk,
    const float* __restrict__ Wv)
{
    int idx = blockIdx.x * 256 + threadIdx.x;
    int mat = idx >> 16;
    int rem = idx & 65535;
    const float* src = (mat == 0) ? Wq : (mat == 1) ? Wk : Wv;
    int h = rem >> 14, d = (rem >> 6) & 255, e = rem & 63;
    float v = src[rem];
    __nv_bfloat16 hi = __float2bfloat16(v);
    size_t dst = (size_t)((mat * HH + h) * DKK + e) * EE + d;
    g_Wh[dst] = hi;
    g_Wl[dst] = __float2bfloat16(v - __bfloat162float(hi));
}

__global__ void __launch_bounds__(256) wosplit_kernel(const float* __restrict__ Wo)
{
    int idx = blockIdx.x * 256 + threadIdx.x;
    float v = Wo[idx];
    __nv_bfloat16 hi = __float2bfloat16(v);
    g_Woh[idx] = hi;
    g_Wol[idx] = __float2bfloat16(v - __bfloat162float(hi));
}

// ---------------------------------------------------------------------------
// Tensor-core QKV projection (unchanged from R7, KPAD layout).
// ---------------------------------------------------------------------------
#define KPAD 72

__global__ void __launch_bounds__(128) qkv_mma_kernel()
{
    __shared__ __nv_bfloat16 Ah[64*KPAD], Al[64*KPAD];
    __shared__ __nv_bfloat16 Bh[64*KPAD], Bl[64*KPAD];

    const int t = threadIdx.x;
    const int w = t >> 5, lane = t & 31;
    const int gq = lane >> 2, q4 = lane & 3;
    const int m0 = blockIdx.x * 64;
    const int n0 = blockIdx.y * 64;

    float acc[8][4];
    #pragma unroll
    for (int nt = 0; nt < 8; nt++)
        #pragma unroll
        for (int j = 0; j < 4; j++) acc[nt][j] = 0.f;

    const u32 AhB = sptr(Ah), AlB = sptr(Al), BhB = sptr(Bh), BlB = sptr(Bl);
    const u32 offA = (u32)(((lane & 7) + (((lane >> 3) & 1) << 3) + w * 16) * (KPAD * 2)
                           + (((lane >> 4) & 1) << 4));
    const u32 offB = (u32)(((lane & 7) + (((lane >> 4) & 1) << 3)) * (KPAD * 2)
                           + (((lane >> 3) & 1) << 4));

    for (int k0 = 0; k0 < EE; k0 += 64) {
        __syncthreads();
        #pragma unroll
        for (int i8 = t * 8; i8 < 64 * 64; i8 += 128 * 8) {
            int row = i8 >> 6, col = i8 & 63;
            int so = row * KPAD + col;
            *(float4*)&Ah[so] = *(const float4*)&g_Xh[(size_t)(m0 + row) * EE + k0 + col];
            *(float4*)&Al[so] = *(const float4*)&g_Xl[(size_t)(m0 + row) * EE + k0 + col];
            *(float4*)&Bh[so] = *(const float4*)&g_Wh[(size_t)(n0 + row) * EE + k0 + col];
            *(float4*)&Bl[so] = *(const float4*)&g_Wl[(size_t)(n0 + row) * EE + k0 + col];
        }
        __syncthreads();

        #pragma unroll
        for (int k16 = 0; k16 < 4; k16++) {
            u32 ah[4], al[4];
            ldsm4(ah[0], ah[1], ah[2], ah[3], AhB + offA + k16 * 32);
            ldsm4(al[0], al[1], al[2], al[3], AlB + offA + k16 * 32);
            #pragma unroll
            for (int ntp = 0; ntp < 4; ntp++) {
                u32 b0, b1, b2, b3, c0, c1, c2, c3;
                u32 ad = offB + (u32)(ntp * 16 * KPAD * 2 + k16 * 32);
                ldsm4(b0, b1, b2, b3, BhB + ad);
                ldsm4(c0, c1, c2, c3, BlB + ad);
                MMA(acc[2*ntp],     ah, b0, b1);
                MMA(acc[2*ntp],     ah, c0, c1);
                MMA(acc[2*ntp],     al, b0, b1);
                MMA(acc[2*ntp + 1], ah, b2, b3);
                MMA(acc[2*ntp + 1], ah, c2, c3);
                MMA(acc[2*ntp + 1], al, b2, b3);
            }
        }
    }

    const int mat = n0 >> 8, h = (n0 >> 6) & 3;
    __nv_bfloat16* dh = (mat == 0) ? g_Qh : (mat == 1) ? g_Kh : g_Vh;
    __nv_bfloat16* dl = (mat == 0) ? g_Ql : (mat == 1) ? g_Kl : g_Vl;
    const float mult = (mat == 0) ? QSCALE : 1.0f;

    const int r0 = m0 + w * 16 + gq;
    const int b0_ = r0 >> 11, n2_0 = r0 & 2047;
    const int b1_ = (r0 + 8) >> 11, n2_1 = (r0 + 8) & 2047;
    #pragma unroll
    for (int nt = 0; nt < 8; nt++) {
        int c = nt * 8 + q4 * 2;
        u32 hi, lo;
        split2(acc[nt][0] * mult, acc[nt][1] * mult, hi, lo);
        size_t a0 = ((size_t)((b0_ * HH + h) * NN + n2_0)) * DKK + c;
        *(u32*)&dh[a0] = hi; *(u32*)&dl[a0] = lo;
        split2(acc[nt][2] * mult, acc[nt][3] * mult, hi, lo);
        size_t a1 = ((size_t)((b1_ * HH + h) * NN + n2_1)) * DKK + c;
        *(u32*)&dh[a1] = hi; *(u32*)&dl[a1] = lo;
    }
}

// ---------------------------------------------------------------------------
// Flash attention with cp.async double-buffered pipeline.
// Dynamic smem: 2 stages x (Kh,Kl,Vh,Vl) x 64x64 bf16 = 65536 B.
// Layout per array: row-major [key/row][64 d], XOR-swizzled per 16B unit:
//   addr(row, u) = row*128 + ((u ^ (row & 7)) << 4)   (u = d>>3)
// -> cp.async 16B aligned, ldmatrix / ldmatrix.trans conflict-free.
// ---------------------------------------------------------------------------
#define STAGE_B 32768   // bytes per stage (4 arrays x 8192)

extern __shared__ __nv_bfloat16 dynsmem[];

__global__ void __launch_bounds__(128) attn_kernel()
{
    const int t = threadIdx.x;
    const int w = t >> 5, lane = t & 31;
    const int gq = lane >> 2, q4 = lane & 3;
    const int q0 = blockIdx.x * 64;
    const int bh = blockIdx.y;
    const int b  = bh >> 2, h = bh & 3;

    const int r0 = q0 + w * 16 + gq;

    // ---- Q fragments: direct bf16x2 loads from pre-split globals ----
    u32 qh[4][4], ql[4][4];
    {
        const __nv_bfloat16* Qh = g_Qh + (size_t)bh * NN * DKK;
        const __nv_bfloat16* Ql = g_Ql + (size_t)bh * NN * DKK;
        #pragma unroll
        for (int kc = 0; kc < 4; kc++) {
            int c = kc * 16 + q4 * 2;
            qh[kc][0] = *(const u32*)&Qh[(size_t)(r0    ) * DKK + c    ];
            qh[kc][1] = *(const u32*)&Qh[(size_t)(r0 + 8) * DKK + c    ];
            qh[kc][2] = *(const u32*)&Qh[(size_t)(r0    ) * DKK + c + 8];
            qh[kc][3] = *(const u32*)&Qh[(size_t)(r0 + 8) * DKK + c + 8];
            ql[kc][0] = *(const u32*)&Ql[(size_t)(r0    ) * DKK + c    ];
            ql[kc][1] = *(const u32*)&Ql[(size_t)(r0 + 8) * DKK + c    ];
            ql[kc][2] = *(const u32*)&Ql[(size_t)(r0    ) * DKK + c + 8];
            ql[kc][3] = *(const u32*)&Ql[(size_t)(r0 + 8) * DKK + c + 8];
        }
    }

    float o[8][4];
    #pragma unroll
    for (int nt = 0; nt < 8; nt++)
        #pragma unroll
        for (int j = 0; j < 4; j++) o[nt][j] = 0.f;
    float l0 = 0.f, l1 = 0.f;

    const u64* mr0 = (const u64*)g_mask + ((size_t)(b * NN + r0    )) * (NN / 64);
    const u64* mr1 = (const u64*)g_mask + ((size_t)(b * NN + r0 + 8)) * (NN / 64);

    const u32 smemB = sptr(dynsmem);

    // per-thread swizzled ldmatrix offsets (within one array)
    const int rS  = (lane & 7) + ((lane >> 4) << 3);
    const int ubS = (lane >> 3) & 1;
    u32 swzS[4];
    #pragma unroll
    for (int kc = 0; kc < 4; kc++)
        swzS[kc] = (u32)(rS * 128 + (((kc * 2 + ubS) ^ (rS & 7)) << 4));
    const int rV  = (lane & 7) + (((lane >> 3) & 1) << 3);
    const int ubV = (lane >> 4) & 1;
    u32 swzV[4];
    #pragma unroll
    for (int ntp = 0; ntp < 4; ntp++)
        swzV[ntp] = (u32)(rV * 128 + (((ntp * 2 + ubV) ^ (rV & 7)) << 4));

    const __nv_bfloat16* baseKh = g_Kh + (size_t)bh * NN * DKK;
    const __nv_bfloat16* baseKl = g_Kl + (size_t)bh * NN * DKK;
    const __nv_bfloat16* baseVh = g_Vh + (size_t)bh * NN * DKK;
    const __nv_bfloat16* baseVl = g_Vl + (size_t)bh * NN * DKK;

    // async fill of one stage with tile at key offset k0
    auto fill = [&](int stage, int k0) {
        u32 dstB = smemB + stage * STAGE_B;
        const char* sKh = (const char*)(baseKh + (size_t)k0 * DKK);
        const char* sKl = (const char*)(baseKl + (size_t)k0 * DKK);
        const char* sVh = (const char*)(baseVh + (size_t)k0 * DKK);
        const char* sVl = (const char*)(baseVl + (size_t)k0 * DKK);
        #pragma unroll
        for (int i = 0; i < 4; i++) {
            int chunk = t + i * 128;               // 0..511
            int row = chunk >> 3, u = chunk & 7;
            u32 doff = (u32)(row * 128 + ((u ^ (row & 7)) << 4));
            int soff = row * 128 + u * 16;
            cpa16(dstB +             doff, sKh + soff);
            cpa16(dstB +  8192     + doff, sKl + soff);
            cpa16(dstB + 16384     + doff, sVh + soff);
            cpa16(dstB + 24576     + doff, sVl + soff);
        }
    };

    fill(0, 0);
    asm volatile("cp.async.commit_group;" ::: "memory");

    for (int k0 = 0; k0 < NN; k0 += 64) {
        const int stage = (k0 >> 6) & 1;
        if (k0 + 64 < NN) {
            fill(stage ^ 1, k0 + 64);
            asm volatile("cp.async.commit_group;" ::: "memory");
            asm volatile("cp.async.wait_group 1;" ::: "memory");
        } else {
            asm volatile("cp.async.wait_group 0;" ::: "memory");
        }
        __syncthreads();

        const u32 stB = smemB + stage * STAGE_B;
        const u32 KhB = stB, KlB = stB + 8192, VhB = stB + 16384, VlB = stB + 24576;

        // ---- S = Q K^T ----
        float s[8][4];
        #pragma unroll
        for (int nt = 0; nt < 8; nt++)
            #pragma unroll
            for (int j = 0; j < 4; j++) s[nt][j] = 0.f;

        #pragma unroll
        for (int kc = 0; kc < 4; kc++) {
            #pragma unroll
            for (int ntp = 0; ntp < 4; ntp++) {
                u32 a0, a1, a2, a3, c0, c1, c2, c3;
                u32 ad = (u32)(ntp * 2048) + swzS[kc];
                ldsm4(a0, a1, a2, a3, KhB + ad);
                ldsm4(c0, c1, c2, c3, KlB + ad);
                MMA(s[2*ntp],     qh[kc], a0, a1);
                MMA(s[2*ntp],     qh[kc], c0, c1);
                MMA(s[2*ntp],     ql[kc], a0, a1);
                MMA(s[2*ntp + 1], qh[kc], a2, a3);
                MMA(s[2*ntp + 1], qh[kc], c2, c3);
                MMA(s[2*ntp + 1], ql[kc], a2, a3);
            }
        }

        // ---- masked exp (log2 domain), pack P fragments ----
        u64 m0 = mr0[k0 >> 6];
        u64 m1 = mr1[k0 >> 6];
        u32 ph[8], ph2[8], pl[8], pl2[8];
        #pragma unroll
        for (int nt = 0; nt < 8; nt++) {
            int pos = nt * 8 + q4 * 2;
            float p0 = ((m0 >> pos)       & 1) ? ex2f(s[nt][0]) : 0.f;
            float p1 = ((m0 >> (pos + 1)) & 1) ? ex2f(s[nt][1]) : 0.f;
            float p2 = ((m1 >> pos)       & 1) ? ex2f(s[nt][2]) : 0.f;
            float p3 = ((m1 >> (pos + 1)) & 1) ? ex2f(s[nt][3]) : 0.f;
            l0 += p0 + p1;
            l1 += p2 + p3;
            split2(p0, p1, ph[nt],  pl[nt]);
            split2(p2, p3, ph2[nt], pl2[nt]);
        }

        // ---- O += P V ----
        #pragma unroll
        for (int tt = 0; tt < 4; tt++) {
            u32 ah[4] = {ph[2*tt], ph2[2*tt], ph[2*tt+1], ph2[2*tt+1]};
            u32 al[4] = {pl[2*tt], pl2[2*tt], pl[2*tt+1], pl2[2*tt+1]};
            #pragma unroll
            for (int ntp = 0; ntp < 4; ntp++) {
                u32 h0, h1, h2, h3, e0, e1, e2, e3;
                u32 ad = (u32)(tt * 2048) + swzV[ntp];
                ldsm4t(h0, h1, h2, h3, VhB + ad);
                ldsm4t(e0, e1, e2, e3, VlB + ad);
                MMA(o[2*ntp],     ah, h0, h1);
                MMA(o[2*ntp],     ah, e0, e1);
                MMA(o[2*ntp],     al, h0, h1);
                MMA(o[2*ntp + 1], ah, h2, h3);
                MMA(o[2*ntp + 1], ah, e2, e3);
                MMA(o[2*ntp + 1], al, h2, h3);
            }
        }
        __syncthreads();   // all reads of this stage done before its refill
    }

    // ---- epilogue: reduce l, split C into hi/lo bf16 ----
    l0 += __shfl_xor_sync(0xffffffffu, l0, 1);
    l0 += __shfl_xor_sync(0xffffffffu, l0, 2);
    l1 += __shfl_xor_sync(0xffffffffu, l1, 1);
    l1 += __shfl_xor_sync(0xffffffffu, l1, 2);
    float inv0 = 1.f / l0, inv1 = 1.f / l1;

    #pragma unroll
    for (int nt = 0; nt < 8; nt++) {
        int d = h * DKK + nt * 8 + q4 * 2;
        u32 hi, lo;
        split2(o[nt][0] * inv0, o[nt][1] * inv0, hi, lo);
        size_t a0 = ((size_t)(b * NN) + r0) * EE + d;
        *(u32*)&g_Ch[a0] = hi; *(u32*)&g_Cl[a0] = lo;
        split2(o[nt][2] * inv1, o[nt][3] * inv1, hi, lo);
        size_t a1 = ((size_t)(b * NN) + r0 + 8) * EE + d;
        *(u32*)&g_Ch[a1] = hi; *(u32*)&g_Cl[a1] = lo;
    }
}

// ---------------------------------------------------------------------------
// Tensor-core output projection (unchanged from R7).
// ---------------------------------------------------------------------------
__global__ void __launch_bounds__(128) out_mma_kernel(
    const float* __restrict__ bo, float* __restrict__ out)
{
    __shared__ __nv_bfloat16 Ah[64*KPAD], Al[64*KPAD];
    __shared__ __nv_bfloat16 Bh[64*KPAD], Bl[64*KPAD];

    const int t = threadIdx.x;
    const int w = t >> 5, lane = t & 31;
    const int gq = lane >> 2, q4 = lane & 3;
    const int m0 = blockIdx.x * 64;
    const int n0 = blockIdx.y * 64;

    float acc[8][4];
    #pragma unroll
    for (int nt = 0; nt < 8; nt++)
        #pragma unroll
        for (int j = 0; j < 4; j++) acc[nt][j] = 0.f;

    const u32 AhB = sptr(Ah), AlB = sptr(Al), BhB = sptr(Bh), BlB = sptr(Bl);
    const u32 offA = (u32)(((lane & 7) + (((lane >> 3) & 1) << 3) + w * 16) * (KPAD * 2)
                           + (((lane >> 4) & 1) << 4));
    const u32 offB = (u32)(((lane & 7) + (((lane >> 4) & 1) << 3)) * (KPAD * 2)
                           + (((lane >> 3) & 1) << 4));

    for (int k0 = 0; k0 < EE; k0 += 64) {
        __syncthreads();
        #pragma unroll
        for (int i8 = t * 8; i8 < 64 * 64; i8 += 128 * 8) {
            int row = i8 >> 6, col = i8 & 63;
            int so = row * KPAD + col;
            *(float4*)&Ah[so] = *(const float4*)&g_Ch[(size_t)(m0 + row) * EE + k0 + col];
            *(float4*)&Al[so] = *(const float4*)&g_Cl[(size_t)(m0 + row) * EE + k0 + col];
            *(float4*)&Bh[so] = *(const float4*)&g_Woh[(size_t)(n0 + row) * EE + k0 + col];
            *(float4*)&Bl[so] = *(const float4*)&g_Wol[(size_t)(n0 + row) * EE + k0 + col];
        }
        __syncthreads();

        #pragma unroll
        for (int k16 = 0; k16 < 4; k16++) {
            u32 ah[4], al[4];
            ldsm4(ah[0], ah[1], ah[2], ah[3], AhB + offA + k16 * 32);
            ldsm4(al[0], al[1], al[2], al[3], AlB + offA + k16 * 32);
            #pragma unroll
            for (int ntp = 0; ntp < 4; ntp++) {
                u32 b0, b1, b2, b3, c0, c1, c2, c3;
                u32 ad = offB + (u32)(ntp * 16 * KPAD * 2 + k16 * 32);
                ldsm4(b0, b1, b2, b3, BhB + ad);
                ldsm4(c0, c1, c2, c3, BlB + ad);
                MMA(acc[2*ntp],     ah, b0, b1);
                MMA(acc[2*ntp],     ah, c0, c1);
                MMA(acc[2*ntp],     al, b0, b1);
                MMA(acc[2*ntp + 1], ah, b2, b3);
                MMA(acc[2*ntp + 1], ah, c2, c3);
                MMA(acc[2*ntp + 1], al, b2, b3);
            }
        }
    }

    const int r0 = m0 + w * 16 + gq;
    #pragma unroll
    for (int nt = 0; nt < 8; nt++) {
        int c = n0 + nt * 8 + q4 * 2;
        float2 bv = *(const float2*)&bo[c];
        float2 v0 = make_float2(acc[nt][0] + bv.x, acc[nt][1] + bv.y);
        float2 v1 = make_float2(acc[nt][2] + bv.x, acc[nt][3] + bv.y);
        *(float2*)&out[(size_t)(r0    ) * EE + c] = v0;
        *(float2*)&out[(size_t)(r0 + 8) * EE + c] = v1;
    }
}

// ---------------------------------------------------------------------------
extern "C" void kernel_launch(void* const* d_in, const int* in_sizes, int n_in,
                              void* d_out, int out_size)
{
    const float* X   = (const float*)d_in[0];
    const int*   Adj = (const int*)  d_in[1];
    const float* Wq  = (const float*)d_in[2];
    const float* Wk  = (const float*)d_in[3];
    const float* Wv  = (const float*)d_in[4];
    const float* Wo  = (const float*)d_in[5];
    const float* bo  = (const float*)d_in[6];
    float* out = (float*)d_out;

    static int smem_set = 0;
    if (!smem_set) {
        cudaFuncSetAttribute(attn_kernel,
            cudaFuncAttributeMaxDynamicSharedMemorySize, 2 * STAGE_B);
        smem_set = 1;
    }

    mask_kernel<<<BB*NN*NN/256, 256>>>(Adj);
    xsplit_kernel<<<MTOT*EE/1024, 256>>>(X);
    wsplit_kernel<<<768, 256>>>(Wq, Wk, Wv);
    wosplit_kernel<<<256, 256>>>(Wo);
    qkv_mma_kernel<<<dim3(MTOT/64, 12), 128>>>();
    attn_kernel<<<dim3(NN/64, BB*HH), 128, 2*STAGE_B>>>();
    out_mma_kernel<<<dim3(MTOT/64, 4), 128>>>(bo, out);
}

// round 9
// speedup vs baseline: 1.1222x; 1.1222x over previous
#include <cuda_runtime.h>
#include <cuda_bf16.h>
#include <math.h>
#include <stdint.h>
#include <stddef.h>

#define BB 2
#define NN 2048
#define EE 256
#define HH 4
#define DKK 64
#define MTOT (BB*NN)

// 1/sqrt(64) * log2(e): scores produced in log2 domain for ex2-softmax
#define QSCALE 0.1803368801111204f

typedef unsigned int u32;
typedef unsigned long long u64;

__device__ __forceinline__ float ex2f(float x) {
    float r; asm("ex2.approx.f32 %0, %1;" : "=f"(r) : "f"(x)); return r;
}
__device__ __forceinline__ u32 sptr(const void* p) {
    return (u32)__cvta_generic_to_shared(p);
}
__device__ __forceinline__ void ldsm4(u32& r0, u32& r1, u32& r2, u32& r3, u32 a) {
    asm volatile("ldmatrix.sync.aligned.m8n8.x4.shared.b16 {%0,%1,%2,%3}, [%4];"
        : "=r"(r0), "=r"(r1), "=r"(r2), "=r"(r3) : "r"(a));
}
__device__ __forceinline__ void ldsm4t(u32& r0, u32& r1, u32& r2, u32& r3, u32 a) {
    asm volatile("ldmatrix.sync.aligned.m8n8.x4.trans.shared.b16 {%0,%1,%2,%3}, [%4];"
        : "=r"(r0), "=r"(r1), "=r"(r2), "=r"(r3) : "r"(a));
}
__device__ __forceinline__ void cpa16(u32 dst, const void* src) {
    asm volatile("cp.async.cg.shared.global [%0], [%1], 16;" :: "r"(dst), "l"(src));
}

// Scratch: everything the hot kernels touch is pre-split bf16 hi/lo.
__device__ __align__(16) __nv_bfloat16 g_Xh[MTOT*EE],  g_Xl[MTOT*EE];
__device__ __align__(16) __nv_bfloat16 g_Wh[12*DKK*EE], g_Wl[12*DKK*EE];
__device__ __align__(16) __nv_bfloat16 g_Woh[EE*EE],   g_Wol[EE*EE];
__device__ __align__(16) __nv_bfloat16 g_Qh[BB*HH*NN*DKK], g_Ql[BB*HH*NN*DKK];
__device__ __align__(16) __nv_bfloat16 g_Kh[BB*HH*NN*DKK], g_Kl[BB*HH*NN*DKK];
__device__ __align__(16) __nv_bfloat16 g_Vh[BB*HH*NN*DKK], g_Vl[BB*HH*NN*DKK];
__device__ __align__(16) __nv_bfloat16 g_Ch[MTOT*EE],  g_Cl[MTOT*EE];
__device__ u32 g_mask[BB*NN*NN/32];

// fast bf16 hi/lo split of a float pair:
//   hi = cvt.rn.bf16x2(y, x);  residuals via bit-exact bf16->f32 (shift/mask)
__device__ __forceinline__ void split2(float x, float y, u32& hi, u32& lo) {
    asm("cvt.rn.bf16x2.f32 %0, %1, %2;" : "=r"(hi) : "f"(y), "f"(x));
    float hx = __uint_as_float(hi << 16);
    float hy = __uint_as_float(hi & 0xffff0000u);
    float rx = x - hx, ry = y - hy;
    asm("cvt.rn.bf16x2.f32 %0, %1, %2;" : "=r"(lo) : "f"(ry), "f"(rx));
}

#define MMA(d, a, b0_, b1_) asm volatile( \
    "mma.sync.aligned.m16n8k16.row.col.f32.bf16.bf16.f32 " \
    "{%0,%1,%2,%3}, {%4,%5,%6,%7}, {%8,%9}, {%0,%1,%2,%3};" \
    : "+f"(d[0]), "+f"(d[1]), "+f"(d[2]), "+f"(d[3]) \
    : "r"(a[0]), "r"(a[1]), "r"(a[2]), "r"(a[3]), "r"(b0_), "r"(b1_))

// ---------------------------------------------------------------------------
// Merged prep: adjacency bitmask + X split + W transpose/split + Wo split.
// blockIdx ranges: [0,32768) mask, [32768,33792) xsplit, [33792,34560) wsplit,
// [34560,34816) wosplit. One launch instead of four.
// ---------------------------------------------------------------------------
__global__ void __launch_bounds__(256) prep_kernel(
    const int* __restrict__ Adj, const float* __restrict__ X,
    const float* __restrict__ Wq, const float* __restrict__ Wk,
    const float* __restrict__ Wv, const float* __restrict__ Wo)
{
    const int bid = blockIdx.x;
    const int t = threadIdx.x;

    if (bid < 32768) {                       // ---- adjacency bitmask ----
        int gid  = bid * 256 + t;
        int word = gid >> 5, lane = gid & 31;
        int v = Adj[(size_t)word * 32 + lane];
        u32 m = __ballot_sync(0xffffffffu, v > 0);
        if (lane == 0) g_mask[word] = m;
    } else if (bid < 33792) {                // ---- X split ----
        int i = ((bid - 32768) * 256 + t) * 4;
        float4 v = *(const float4*)&X[i];
        u32 h0, l0, h1, l1;
        split2(v.x, v.y, h0, l0);
        split2(v.z, v.w, h1, l1);
        *(u32*)&g_Xh[i]     = h0; *(u32*)&g_Xh[i + 2] = h1;
        *(u32*)&g_Xl[i]     = l0; *(u32*)&g_Xl[i + 2] = l1;
    } else if (bid < 34560) {                // ---- Wq/Wk/Wv transpose+split ----
        int idx = (bid - 33792) * 256 + t;
        int mat = idx >> 16;
        int rem = idx & 65535;
        const float* src = (mat == 0) ? Wq : (mat == 1) ? Wk : Wv;
        int h = rem >> 14, d = (rem >> 6) & 255, e = rem & 63;
        float v = src[rem];
        __nv_bfloat16 hi = __float2bfloat16(v);
        size_t dst = (size_t)((mat * HH + h) * DKK + e) * EE + d;
        g_Wh[dst] = hi;
        g_Wl[dst] = __float2bfloat16(v - __bfloat162float(hi));
    } else {                                 // ---- Wo split ----
        int idx = (bid - 34560) * 256 + t;
        float v = Wo[idx];
        __nv_bfloat16 hi = __float2bfloat16(v);
        g_Woh[idx] = hi;
        g_Wol[idx] = __float2bfloat16(v - __bfloat162float(hi));
    }
}

// ---------------------------------------------------------------------------
// Tensor-core QKV projection (unchanged structure).
// ---------------------------------------------------------------------------
#define KPAD 72

__global__ void __launch_bounds__(128) qkv_mma_kernel()
{
    __shared__ __nv_bfloat16 Ah[64*KPAD], Al[64*KPAD];
    __shared__ __nv_bfloat16 Bh[64*KPAD], Bl[64*KPAD];

    const int t = threadIdx.x;
    const int w = t >> 5, lane = t & 31;
    const int gq = lane >> 2, q4 = lane & 3;
    const int m0 = blockIdx.x * 64;
    const int n0 = blockIdx.y * 64;

    float acc[8][4];
    #pragma unroll
    for (int nt = 0; nt < 8; nt++)
        #pragma unroll
        for (int j = 0; j < 4; j++) acc[nt][j] = 0.f;

    const u32 AhB = sptr(Ah), AlB = sptr(Al), BhB = sptr(Bh), BlB = sptr(Bl);
    const u32 offA = (u32)(((lane & 7) + (((lane >> 3) & 1) << 3) + w * 16) * (KPAD * 2)
                           + (((lane >> 4) & 1) << 4));
    const u32 offB = (u32)(((lane & 7) + (((lane >> 4) & 1) << 3)) * (KPAD * 2)
                           + (((lane >> 3) & 1) << 4));

    for (int k0 = 0; k0 < EE; k0 += 64) {
        __syncthreads();
        #pragma unroll
        for (int i8 = t * 8; i8 < 64 * 64; i8 += 128 * 8) {
            int row = i8 >> 6, col = i8 & 63;
            int so = row * KPAD + col;
            *(float4*)&Ah[so] = *(const float4*)&g_Xh[(size_t)(m0 + row) * EE + k0 + col];
            *(float4*)&Al[so] = *(const float4*)&g_Xl[(size_t)(m0 + row) * EE + k0 + col];
            *(float4*)&Bh[so] = *(const float4*)&g_Wh[(size_t)(n0 + row) * EE + k0 + col];
            *(float4*)&Bl[so] = *(const float4*)&g_Wl[(size_t)(n0 + row) * EE + k0 + col];
        }
        __syncthreads();

        #pragma unroll
        for (int k16 = 0; k16 < 4; k16++) {
            u32 ah[4], al[4];
            ldsm4(ah[0], ah[1], ah[2], ah[3], AhB + offA + k16 * 32);
            ldsm4(al[0], al[1], al[2], al[3], AlB + offA + k16 * 32);
            #pragma unroll
            for (int ntp = 0; ntp < 4; ntp++) {
                u32 b0, b1, b2, b3, c0, c1, c2, c3;
                u32 ad = offB + (u32)(ntp * 16 * KPAD * 2 + k16 * 32);
                ldsm4(b0, b1, b2, b3, BhB + ad);
                ldsm4(c0, c1, c2, c3, BlB + ad);
                MMA(acc[2*ntp],     ah, b0, b1);
                MMA(acc[2*ntp],     ah, c0, c1);
                MMA(acc[2*ntp],     al, b0, b1);
                MMA(acc[2*ntp + 1], ah, b2, b3);
                MMA(acc[2*ntp + 1], ah, c2, c3);
                MMA(acc[2*ntp + 1], al, b2, b3);
            }
        }
    }

    const int mat = n0 >> 8, h = (n0 >> 6) & 3;
    __nv_bfloat16* dh = (mat == 0) ? g_Qh : (mat == 1) ? g_Kh : g_Vh;
    __nv_bfloat16* dl = (mat == 0) ? g_Ql : (mat == 1) ? g_Kl : g_Vl;
    const float mult = (mat == 0) ? QSCALE : 1.0f;

    const int r0 = m0 + w * 16 + gq;
    const int b0_ = r0 >> 11, n2_0 = r0 & 2047;
    const int b1_ = (r0 + 8) >> 11, n2_1 = (r0 + 8) & 2047;
    #pragma unroll
    for (int nt = 0; nt < 8; nt++) {
        int c = nt * 8 + q4 * 2;
        u32 hi, lo;
        split2(acc[nt][0] * mult, acc[nt][1] * mult, hi, lo);
        size_t a0 = ((size_t)((b0_ * HH + h) * NN + n2_0)) * DKK + c;
        *(u32*)&dh[a0] = hi; *(u32*)&dl[a0] = lo;
        split2(acc[nt][2] * mult, acc[nt][3] * mult, hi, lo);
        size_t a1 = ((size_t)((b1_ * HH + h) * NN + n2_1)) * DKK + c;
        *(u32*)&dh[a1] = hi; *(u32*)&dl[a1] = lo;
    }
}

// ---------------------------------------------------------------------------
// Flash attention: fused per-16-key-chunk S -> softmax -> PV.
// Block = 128 thr; cp.async double-buffered smem (2 x 32 KB dynamic).
// Register-lean (no s[8]/p[8] arrays) -> target 3 CTAs/SM.
// ---------------------------------------------------------------------------
#define STAGE_B 32768

extern __shared__ __nv_bfloat16 dynsmem[];

__global__ void __launch_bounds__(128, 3) attn_kernel()
{
    const int t = threadIdx.x;
    const int w = t >> 5, lane = t & 31;
    const int gq = lane >> 2, q4 = lane & 3;
    const int q0 = blockIdx.x * 64;
    const int bh = blockIdx.y;
    const int b  = bh >> 2, h = bh & 3;

    const int r0 = q0 + w * 16 + gq;

    // ---- Q fragments: direct bf16x2 loads from pre-split globals ----
    u32 qh[4][4], ql[4][4];
    {
        const __nv_bfloat16* Qh = g_Qh + (size_t)bh * NN * DKK;
        const __nv_bfloat16* Ql = g_Ql + (size_t)bh * NN * DKK;
        #pragma unroll
        for (int kc = 0; kc < 4; kc++) {
            int c = kc * 16 + q4 * 2;
            qh[kc][0] = *(const u32*)&Qh[(size_t)(r0    ) * DKK + c    ];
            qh[kc][1] = *(const u32*)&Qh[(size_t)(r0 + 8) * DKK + c    ];
            qh[kc][2] = *(const u32*)&Qh[(size_t)(r0    ) * DKK + c + 8];
            qh[kc][3] = *(const u32*)&Qh[(size_t)(r0 + 8) * DKK + c + 8];
            ql[kc][0] = *(const u32*)&Ql[(size_t)(r0    ) * DKK + c    ];
            ql[kc][1] = *(const u32*)&Ql[(size_t)(r0 + 8) * DKK + c    ];
            ql[kc][2] = *(const u32*)&Ql[(size_t)(r0    ) * DKK + c + 8];
            ql[kc][3] = *(const u32*)&Ql[(size_t)(r0 + 8) * DKK + c + 8];
        }
    }

    float o[8][4];
    #pragma unroll
    for (int nt = 0; nt < 8; nt++)
        #pragma unroll
        for (int j = 0; j < 4; j++) o[nt][j] = 0.f;
    float l0 = 0.f, l1 = 0.f;

    const u64* mr0 = (const u64*)g_mask + ((size_t)(b * NN + r0    )) * (NN / 64);
    const u64* mr1 = (const u64*)g_mask + ((size_t)(b * NN + r0 + 8)) * (NN / 64);

    const u32 smemB = sptr(dynsmem);

    const int rS  = (lane & 7) + ((lane >> 4) << 3);
    const int ubS = (lane >> 3) & 1;
    u32 swzS[4];
    #pragma unroll
    for (int kc = 0; kc < 4; kc++)
        swzS[kc] = (u32)(rS * 128 + (((kc * 2 + ubS) ^ (rS & 7)) << 4));
    const int rV  = (lane & 7) + (((lane >> 3) & 1) << 3);
    const int ubV = (lane >> 4) & 1;
    u32 swzV[4];
    #pragma unroll
    for (int ntp = 0; ntp < 4; ntp++)
        swzV[ntp] = (u32)(rV * 128 + (((ntp * 2 + ubV) ^ (rV & 7)) << 4));

    const __nv_bfloat16* baseKh = g_Kh + (size_t)bh * NN * DKK;
    const __nv_bfloat16* baseKl = g_Kl + (size_t)bh * NN * DKK;
    const __nv_bfloat16* baseVh = g_Vh + (size_t)bh * NN * DKK;
    const __nv_bfloat16* baseVl = g_Vl + (size_t)bh * NN * DKK;

    auto fill = [&](int stage, int k0) {
        u32 dstB = smemB + stage * STAGE_B;
        const char* sKh = (const char*)(baseKh + (size_t)k0 * DKK);
        const char* sKl = (const char*)(baseKl + (size_t)k0 * DKK);
        const char* sVh = (const char*)(baseVh + (size_t)k0 * DKK);
        const char* sVl = (const char*)(baseVl + (size_t)k0 * DKK);
        #pragma unroll
        for (int i = 0; i < 4; i++) {
            int chunk = t + i * 128;
            int row = chunk >> 3, u = chunk & 7;
            u32 doff = (u32)(row * 128 + ((u ^ (row & 7)) << 4));
            int soff = row * 128 + u * 16;
            cpa16(dstB +         doff, sKh + soff);
            cpa16(dstB +  8192 + doff, sKl + soff);
            cpa16(dstB + 16384 + doff, sVh + soff);
            cpa16(dstB + 24576 + doff, sVl + soff);
        }
    };

    fill(0, 0);
    asm volatile("cp.async.commit_group;" ::: "memory");

    for (int k0 = 0; k0 < NN; k0 += 64) {
        const int stage = (k0 >> 6) & 1;
        if (k0 + 64 < NN) {
            fill(stage ^ 1, k0 + 64);
            asm volatile("cp.async.commit_group;" ::: "memory");
            asm volatile("cp.async.wait_group 1;" ::: "memory");
        } else {
            asm volatile("cp.async.wait_group 0;" ::: "memory");
        }
        __syncthreads();

        const u32 stB = smemB + stage * STAGE_B;
        const u32 KhB = stB, KlB = stB + 8192, VhB = stB + 16384, VlB = stB + 24576;

        const u64 m0 = mr0[k0 >> 6];
        const u64 m1 = mr1[k0 >> 6];

        // ---- fused: per 16-key chunk tt: S-MMAs -> softmax -> PV-MMAs ----
        #pragma unroll
        for (int tt = 0; tt < 4; tt++) {
            float s0[4] = {0.f, 0.f, 0.f, 0.f};
            float s1[4] = {0.f, 0.f, 0.f, 0.f};
            #pragma unroll
            for (int kc = 0; kc < 4; kc++) {
                u32 a0, a1, a2, a3, c0, c1, c2, c3;
                u32 ad = (u32)(tt * 2048) + swzS[kc];
                ldsm4(a0, a1, a2, a3, KhB + ad);
                ldsm4(c0, c1, c2, c3, KlB + ad);
                MMA(s0, qh[kc], a0, a1);
                MMA(s0, qh[kc], c0, c1);
                MMA(s0, ql[kc], a0, a1);
                MMA(s1, qh[kc], a2, a3);
                MMA(s1, qh[kc], c2, c3);
                MMA(s1, ql[kc], a2, a3);
            }

            // masked exp (log2 domain) for key chunks 2tt (s0) and 2tt+1 (s1)
            const int pos0 = tt * 16 + q4 * 2;
            float p00 = ((m0 >> pos0)        & 1) ? ex2f(s0[0]) : 0.f;
            float p01 = ((m0 >> (pos0 + 1))  & 1) ? ex2f(s0[1]) : 0.f;
            float p02 = ((m1 >> pos0)        & 1) ? ex2f(s0[2]) : 0.f;
            float p03 = ((m1 >> (pos0 + 1))  & 1) ? ex2f(s0[3]) : 0.f;
            float p10 = ((m0 >> (pos0 + 8))  & 1) ? ex2f(s1[0]) : 0.f;
            float p11 = ((m0 >> (pos0 + 9))  & 1) ? ex2f(s1[1]) : 0.f;
            float p12 = ((m1 >> (pos0 + 8))  & 1) ? ex2f(s1[2]) : 0.f;
            float p13 = ((m1 >> (pos0 + 9))  & 1) ? ex2f(s1[3]) : 0.f;
            l0 += (p00 + p01) + (p10 + p11);
            l1 += (p02 + p03) + (p12 + p13);

            u32 ah[4], al[4];
            split2(p00, p01, ah[0], al[0]);
            split2(p02, p03, ah[1], al[1]);
            split2(p10, p11, ah[2], al[2]);
            split2(p12, p13, ah[3], al[3]);

            // PV for this key chunk
            #pragma unroll
            for (int ntp = 0; ntp < 4; ntp++) {
                u32 h0, h1, h2, h3, e0, e1, e2, e3;
                u32 ad = (u32)(tt * 2048) + swzV[ntp];
                ldsm4t(h0, h1, h2, h3, VhB + ad);
                ldsm4t(e0, e1, e2, e3, VlB + ad);
                MMA(o[2*ntp],     ah, h0, h1);
                MMA(o[2*ntp],     ah, e0, e1);
                MMA(o[2*ntp],     al, h0, h1);
                MMA(o[2*ntp + 1], ah, h2, h3);
                MMA(o[2*ntp + 1], ah, e2, e3);
                MMA(o[2*ntp + 1], al, h2, h3);
            }
        }
        __syncthreads();   // all reads of this stage done before its refill
    }

    // ---- epilogue: reduce l, split C into hi/lo bf16 ----
    l0 += __shfl_xor_sync(0xffffffffu, l0, 1);
    l0 += __shfl_xor_sync(0xffffffffu, l0, 2);
    l1 += __shfl_xor_sync(0xffffffffu, l1, 1);
    l1 += __shfl_xor_sync(0xffffffffu, l1, 2);
    float inv0 = 1.f / l0, inv1 = 1.f / l1;

    #pragma unroll
    for (int nt = 0; nt < 8; nt++) {
        int d = h * DKK + nt * 8 + q4 * 2;
        u32 hi, lo;
        split2(o[nt][0] * inv0, o[nt][1] * inv0, hi, lo);
        size_t a0 = ((size_t)(b * NN) + r0) * EE + d;
        *(u32*)&g_Ch[a0] = hi; *(u32*)&g_Cl[a0] = lo;
        split2(o[nt][2] * inv1, o[nt][3] * inv1, hi, lo);
        size_t a1 = ((size_t)(b * NN) + r0 + 8) * EE + d;
        *(u32*)&g_Ch[a1] = hi; *(u32*)&g_Cl[a1] = lo;
    }
}

// ---------------------------------------------------------------------------
// Tensor-core output projection (unchanged structure).
// ---------------------------------------------------------------------------
__global__ void __launch_bounds__(128) out_mma_kernel(
    const float* __restrict__ bo, float* __restrict__ out)
{
    __shared__ __nv_bfloat16 Ah[64*KPAD], Al[64*KPAD];
    __shared__ __nv_bfloat16 Bh[64*KPAD], Bl[64*KPAD];

    const int t = threadIdx.x;
    const int w = t >> 5, lane = t & 31;
    const int gq = lane >> 2, q4 = lane & 3;
    const int m0 = blockIdx.x * 64;
    const int n0 = blockIdx.y * 64;

    float acc[8][4];
    #pragma unroll
    for (int nt = 0; nt < 8; nt++)
        #pragma unroll
        for (int j = 0; j < 4; j++) acc[nt][j] = 0.f;

    const u32 AhB = sptr(Ah), AlB = sptr(Al), BhB = sptr(Bh), BlB = sptr(Bl);
    const u32 offA = (u32)(((lane & 7) + (((lane >> 3) & 1) << 3) + w * 16) * (KPAD * 2)
                           + (((lane >> 4) & 1) << 4));
    const u32 offB = (u32)(((lane & 7) + (((lane >> 4) & 1) << 3)) * (KPAD * 2)
                           + (((lane >> 3) & 1) << 4));

    for (int k0 = 0; k0 < EE; k0 += 64) {
        __syncthreads();
        #pragma unroll
        for (int i8 = t * 8; i8 < 64 * 64; i8 += 128 * 8) {
            int row = i8 >> 6, col = i8 & 63;
            int so = row * KPAD + col;
            *(float4*)&Ah[so] = *(const float4*)&g_Ch[(size_t)(m0 + row) * EE + k0 + col];
            *(float4*)&Al[so] = *(const float4*)&g_Cl[(size_t)(m0 + row) * EE + k0 + col];
            *(float4*)&Bh[so] = *(const float4*)&g_Woh[(size_t)(n0 + row) * EE + k0 + col];
            *(float4*)&Bl[so] = *(const float4*)&g_Wol[(size_t)(n0 + row) * EE + k0 + col];
        }
        __syncthreads();

        #pragma unroll
        for (int k16 = 0; k16 < 4; k16++) {
            u32 ah[4], al[4];
            ldsm4(ah[0], ah[1], ah[2], ah[3], AhB + offA + k16 * 32);
            ldsm4(al[0], al[1], al[2], al[3], AlB + offA + k16 * 32);
            #pragma unroll
            for (int ntp = 0; ntp < 4; ntp++) {
                u32 b0, b1, b2, b3, c0, c1, c2, c3;
                u32 ad = offB + (u32)(ntp * 16 * KPAD * 2 + k16 * 32);
                ldsm4(b0, b1, b2, b3, BhB + ad);
                ldsm4(c0, c1, c2, c3, BlB + ad);
                MMA(acc[2*ntp],     ah, b0, b1);
                MMA(acc[2*ntp],     ah, c0, c1);
                MMA(acc[2*ntp],     al, b0, b1);
                MMA(acc[2*ntp + 1], ah, b2, b3);
                MMA(acc[2*ntp + 1], ah, c2, c3);
                MMA(acc[2*ntp + 1], al, b2, b3);
            }
        }
    }

    const int r0 = m0 + w * 16 + gq;
    #pragma unroll
    for (int nt = 0; nt < 8; nt++) {
        int c = n0 + nt * 8 + q4 * 2;
        float2 bv = *(const float2*)&bo[c];
        float2 v0 = make_float2(acc[nt][0] + bv.x, acc[nt][1] + bv.y);
        float2 v1 = make_float2(acc[nt][2] + bv.x, acc[nt][3] + bv.y);
        *(float2*)&out[(size_t)(r0    ) * EE + c] = v0;
        *(float2*)&out[(size_t)(r0 + 8) * EE + c] = v1;
    }
}

// ---------------------------------------------------------------------------
extern "C" void kernel_launch(void* const* d_in, const int* in_sizes, int n_in,
                              void* d_out, int out_size)
{
    const float* X   = (const float*)d_in[0];
    const int*   Adj = (const int*)  d_in[1];
    const float* Wq  = (const float*)d_in[2];
    const float* Wk  = (const float*)d_in[3];
    const float* Wv  = (const float*)d_in[4];
    const float* Wo  = (const float*)d_in[5];
    const float* bo  = (const float*)d_in[6];
    float* out = (float*)d_out;

    cudaFuncSetAttribute(attn_kernel,
        cudaFuncAttributeMaxDynamicSharedMemorySize, 2 * STAGE_B);

    prep_kernel<<<34816, 256>>>(Adj, X, Wq, Wk, Wv, Wo);
    qkv_mma_kernel<<<dim3(MTOT/64, 12), 128>>>();
    attn_kernel<<<dim3(NN/64, BB*HH), 128, 2*STAGE_B>>>();
    out_mma_kernel<<<dim3(MTOT/64, 4), 128>>>(bo, out);
}

// round 10
// speedup vs baseline: 1.1419x; 1.0176x over previous
#include <cuda_runtime.h>
#include <cuda_bf16.h>
#include <math.h>
#include <stdint.h>
#include <stddef.h>

#define BB 2
#define NN 2048
#define EE 256
#define HH 4
#define DKK 64
#define MTOT (BB*NN)

// 1/sqrt(64) * log2(e): scores produced in log2 domain for ex2-softmax
#define QSCALE 0.1803368801111204f

typedef unsigned int u32;
typedef unsigned long long u64;

__device__ __forceinline__ float ex2f(float x) {
    float r; asm("ex2.approx.f32 %0, %1;" : "=f"(r) : "f"(x)); return r;
}
__device__ __forceinline__ u32 sptr(const void* p) {
    return (u32)__cvta_generic_to_shared(p);
}
__device__ __forceinline__ void ldsm4(u32& r0, u32& r1, u32& r2, u32& r3, u32 a) {
    asm volatile("ldmatrix.sync.aligned.m8n8.x4.shared.b16 {%0,%1,%2,%3}, [%4];"
        : "=r"(r0), "=r"(r1), "=r"(r2), "=r"(r3) : "r"(a));
}
__device__ __forceinline__ void ldsm4t(u32& r0, u32& r1, u32& r2, u32& r3, u32 a) {
    asm volatile("ldmatrix.sync.aligned.m8n8.x4.trans.shared.b16 {%0,%1,%2,%3}, [%4];"
        : "=r"(r0), "=r"(r1), "=r"(r2), "=r"(r3) : "r"(a));
}
__device__ __forceinline__ void cpa16(u32 dst, const void* src) {
    asm volatile("cp.async.cg.shared.global [%0], [%1], 16;" :: "r"(dst), "l"(src));
}

// Scratch: everything the hot kernels touch is pre-split bf16 hi/lo.
__device__ __align__(16) __nv_bfloat16 g_Xh[MTOT*EE],  g_Xl[MTOT*EE];
__device__ __align__(16) __nv_bfloat16 g_Wh[12*DKK*EE], g_Wl[12*DKK*EE];
__device__ __align__(16) __nv_bfloat16 g_Woh[EE*EE],   g_Wol[EE*EE];
__device__ __align__(16) __nv_bfloat16 g_Qh[BB*HH*NN*DKK], g_Ql[BB*HH*NN*DKK];
__device__ __align__(16) __nv_bfloat16 g_Kh[BB*HH*NN*DKK], g_Kl[BB*HH*NN*DKK];
__device__ __align__(16) __nv_bfloat16 g_Vh[BB*HH*NN*DKK], g_Vl[BB*HH*NN*DKK];
__device__ __align__(16) __nv_bfloat16 g_Ch[MTOT*EE],  g_Cl[MTOT*EE];
__device__ u32 g_mask[BB*NN*NN/32];

// fast bf16 hi/lo split of a float pair
__device__ __forceinline__ void split2(float x, float y, u32& hi, u32& lo) {
    asm("cvt.rn.bf16x2.f32 %0, %1, %2;" : "=r"(hi) : "f"(y), "f"(x));
    float hx = __uint_as_float(hi << 16);
    float hy = __uint_as_float(hi & 0xffff0000u);
    float rx = x - hx, ry = y - hy;
    asm("cvt.rn.bf16x2.f32 %0, %1, %2;" : "=r"(lo) : "f"(ry), "f"(rx));
}

#define MMA(d, a, b0_, b1_) asm volatile( \
    "mma.sync.aligned.m16n8k16.row.col.f32.bf16.bf16.f32 " \
    "{%0,%1,%2,%3}, {%4,%5,%6,%7}, {%8,%9}, {%0,%1,%2,%3};" \
    : "+f"(d[0]), "+f"(d[1]), "+f"(d[2]), "+f"(d[3]) \
    : "r"(a[0]), "r"(a[1]), "r"(a[2]), "r"(a[3]), "r"(b0_), "r"(b1_))

// ---------------------------------------------------------------------------
// Merged prep (unchanged from R9).
// ---------------------------------------------------------------------------
__global__ void __launch_bounds__(256) prep_kernel(
    const int* __restrict__ Adj, const float* __restrict__ X,
    const float* __restrict__ Wq, const float* __restrict__ Wk,
    const float* __restrict__ Wv, const float* __restrict__ Wo)
{
    const int bid = blockIdx.x;
    const int t = threadIdx.x;

    if (bid < 32768) {
        int gid  = bid * 256 + t;
        int word = gid >> 5, lane = gid & 31;
        int v = Adj[(size_t)word * 32 + lane];
        u32 m = __ballot_sync(0xffffffffu, v > 0);
        if (lane == 0) g_mask[word] = m;
    } else if (bid < 33792) {
        int i = ((bid - 32768) * 256 + t) * 4;
        float4 v = *(const float4*)&X[i];
        u32 h0, l0, h1, l1;
        split2(v.x, v.y, h0, l0);
        split2(v.z, v.w, h1, l1);
        *(u32*)&g_Xh[i]     = h0; *(u32*)&g_Xh[i + 2] = h1;
        *(u32*)&g_Xl[i]     = l0; *(u32*)&g_Xl[i + 2] = l1;
    } else if (bid < 34560) {
        int idx = (bid - 33792) * 256 + t;
        int mat = idx >> 16;
        int rem = idx & 65535;
        const float* src = (mat == 0) ? Wq : (mat == 1) ? Wk : Wv;
        int h = rem >> 14, d = (rem >> 6) & 255, e = rem & 63;
        float v = src[rem];
        __nv_bfloat16 hi = __float2bfloat16(v);
        size_t dst = (size_t)((mat * HH + h) * DKK + e) * EE + d;
        g_Wh[dst] = hi;
        g_Wl[dst] = __float2bfloat16(v - __bfloat162float(hi));
    } else {
        int idx = (bid - 34560) * 256 + t;
        float v = Wo[idx];
        __nv_bfloat16 hi = __float2bfloat16(v);
        g_Woh[idx] = hi;
        g_Wol[idx] = __float2bfloat16(v - __bfloat162float(hi));
    }
}

// ---------------------------------------------------------------------------
// Tensor-core QKV projection (unchanged from R9).
// ---------------------------------------------------------------------------
#define KPAD 72

__global__ void __launch_bounds__(128) qkv_mma_kernel()
{
    __shared__ __nv_bfloat16 Ah[64*KPAD], Al[64*KPAD];
    __shared__ __nv_bfloat16 Bh[64*KPAD], Bl[64*KPAD];

    const int t = threadIdx.x;
    const int w = t >> 5, lane = t & 31;
    const int gq = lane >> 2, q4 = lane & 3;
    const int m0 = blockIdx.x * 64;
    const int n0 = blockIdx.y * 64;

    float acc[8][4];
    #pragma unroll
    for (int nt = 0; nt < 8; nt++)
        #pragma unroll
        for (int j = 0; j < 4; j++) acc[nt][j] = 0.f;

    const u32 AhB = sptr(Ah), AlB = sptr(Al), BhB = sptr(Bh), BlB = sptr(Bl);
    const u32 offA = (u32)(((lane & 7) + (((lane >> 3) & 1) << 3) + w * 16) * (KPAD * 2)
                           + (((lane >> 4) & 1) << 4));
    const u32 offB = (u32)(((lane & 7) + (((lane >> 4) & 1) << 3)) * (KPAD * 2)
                           + (((lane >> 3) & 1) << 4));

    for (int k0 = 0; k0 < EE; k0 += 64) {
        __syncthreads();
        #pragma unroll
        for (int i8 = t * 8; i8 < 64 * 64; i8 += 128 * 8) {
            int row = i8 >> 6, col = i8 & 63;
            int so = row * KPAD + col;
            *(float4*)&Ah[so] = *(const float4*)&g_Xh[(size_t)(m0 + row) * EE + k0 + col];
            *(float4*)&Al[so] = *(const float4*)&g_Xl[(size_t)(m0 + row) * EE + k0 + col];
            *(float4*)&Bh[so] = *(const float4*)&g_Wh[(size_t)(n0 + row) * EE + k0 + col];
            *(float4*)&Bl[so] = *(const float4*)&g_Wl[(size_t)(n0 + row) * EE + k0 + col];
        }
        __syncthreads();

        #pragma unroll
        for (int k16 = 0; k16 < 4; k16++) {
            u32 ah[4], al[4];
            ldsm4(ah[0], ah[1], ah[2], ah[3], AhB + offA + k16 * 32);
            ldsm4(al[0], al[1], al[2], al[3], AlB + offA + k16 * 32);
            #pragma unroll
            for (int ntp = 0; ntp < 4; ntp++) {
                u32 b0, b1, b2, b3, c0, c1, c2, c3;
                u32 ad = offB + (u32)(ntp * 16 * KPAD * 2 + k16 * 32);
                ldsm4(b0, b1, b2, b3, BhB + ad);
                ldsm4(c0, c1, c2, c3, BlB + ad);
                MMA(acc[2*ntp],     ah, b0, b1);
                MMA(acc[2*ntp],     ah, c0, c1);
                MMA(acc[2*ntp],     al, b0, b1);
                MMA(acc[2*ntp + 1], ah, b2, b3);
                MMA(acc[2*ntp + 1], ah, c2, c3);
                MMA(acc[2*ntp + 1], al, b2, b3);
            }
        }
    }

    const int mat = n0 >> 8, h = (n0 >> 6) & 3;
    __nv_bfloat16* dh = (mat == 0) ? g_Qh : (mat == 1) ? g_Kh : g_Vh;
    __nv_bfloat16* dl = (mat == 0) ? g_Ql : (mat == 1) ? g_Kl : g_Vl;
    const float mult = (mat == 0) ? QSCALE : 1.0f;

    const int r0 = m0 + w * 16 + gq;
    const int b0_ = r0 >> 11, n2_0 = r0 & 2047;
    const int b1_ = (r0 + 8) >> 11, n2_1 = (r0 + 8) & 2047;
    #pragma unroll
    for (int nt = 0; nt < 8; nt++) {
        int c = nt * 8 + q4 * 2;
        u32 hi, lo;
        split2(acc[nt][0] * mult, acc[nt][1] * mult, hi, lo);
        size_t a0 = ((size_t)((b0_ * HH + h) * NN + n2_0)) * DKK + c;
        *(u32*)&dh[a0] = hi; *(u32*)&dl[a0] = lo;
        split2(acc[nt][2] * mult, acc[nt][3] * mult, hi, lo);
        size_t a1 = ((size_t)((b1_ * HH + h) * NN + n2_1)) * DKK + c;
        *(u32*)&dh[a1] = hi; *(u32*)&dl[a1] = lo;
    }
}

// ---------------------------------------------------------------------------
// Flash attention: split-K warp groups.
// 256 thr = 8 warps. Group g = warp/4 processes k-tiles (2*it + g)*64.
// Each group owns one 32 KB smem buffer + named barrier (1+g).
// Partial (o, l) of group 1 combined into group 0 via smem at the end.
// ---------------------------------------------------------------------------
#define STAGE_B 32768

extern __shared__ __nv_bfloat16 dynsmem[];

__global__ void __launch_bounds__(256, 2) attn_kernel()
{
    const int t = threadIdx.x;
    const int w = t >> 5, lane = t & 31;
    const int g = w >> 2;          // warp group: 0 even tiles, 1 odd tiles
    const int wg = w & 3;          // row-warp within group
    const int tg = t & 127;        // thread index within group
    const int gq = lane >> 2, q4 = lane & 3;
    const int q0 = blockIdx.x * 64;
    const int bh = blockIdx.y;
    const int b  = bh >> 2, h = bh & 3;

    const int r0 = q0 + wg * 16 + gq;

    // ---- Q fragments ----
    u32 qh[4][4], ql[4][4];
    {
        const __nv_bfloat16* Qh = g_Qh + (size_t)bh * NN * DKK;
        const __nv_bfloat16* Ql = g_Ql + (size_t)bh * NN * DKK;
        #pragma unroll
        for (int kc = 0; kc < 4; kc++) {
            int c = kc * 16 + q4 * 2;
            qh[kc][0] = *(const u32*)&Qh[(size_t)(r0    ) * DKK + c    ];
            qh[kc][1] = *(const u32*)&Qh[(size_t)(r0 + 8) * DKK + c    ];
            qh[kc][2] = *(const u32*)&Qh[(size_t)(r0    ) * DKK + c + 8];
            qh[kc][3] = *(const u32*)&Qh[(size_t)(r0 + 8) * DKK + c + 8];
            ql[kc][0] = *(const u32*)&Ql[(size_t)(r0    ) * DKK + c    ];
            ql[kc][1] = *(const u32*)&Ql[(size_t)(r0 + 8) * DKK + c    ];
            ql[kc][2] = *(const u32*)&Ql[(size_t)(r0    ) * DKK + c + 8];
            ql[kc][3] = *(const u32*)&Ql[(size_t)(r0 + 8) * DKK + c + 8];
        }
    }

    float o[8][4];
    #pragma unroll
    for (int nt = 0; nt < 8; nt++)
        #pragma unroll
        for (int j = 0; j < 4; j++) o[nt][j] = 0.f;
    float l0 = 0.f, l1 = 0.f;

    const u64* mr0 = (const u64*)g_mask + ((size_t)(b * NN + r0    )) * (NN / 64);
    const u64* mr1 = (const u64*)g_mask + ((size_t)(b * NN + r0 + 8)) * (NN / 64);

    const u32 smemB = sptr(dynsmem) + g * STAGE_B;
    const u32 KhB = smemB, KlB = smemB + 8192, VhB = smemB + 16384, VlB = smemB + 24576;

    const int rS  = (lane & 7) + ((lane >> 4) << 3);
    const int ubS = (lane >> 3) & 1;
    u32 swzS[4];
    #pragma unroll
    for (int kc = 0; kc < 4; kc++)
        swzS[kc] = (u32)(rS * 128 + (((kc * 2 + ubS) ^ (rS & 7)) << 4));
    const int rV  = (lane & 7) + (((lane >> 3) & 1) << 3);
    const int ubV = (lane >> 4) & 1;
    u32 swzV[4];
    #pragma unroll
    for (int ntp = 0; ntp < 4; ntp++)
        swzV[ntp] = (u32)(rV * 128 + (((ntp * 2 + ubV) ^ (rV & 7)) << 4));

    const __nv_bfloat16* baseKh = g_Kh + (size_t)bh * NN * DKK;
    const __nv_bfloat16* baseKl = g_Kl + (size_t)bh * NN * DKK;
    const __nv_bfloat16* baseVh = g_Vh + (size_t)bh * NN * DKK;
    const __nv_bfloat16* baseVl = g_Vl + (size_t)bh * NN * DKK;

    for (int it = 0; it < 16; it++) {
        const int k0 = it * 128 + g * 64;

        // ---- fill own buffer (group's 128 threads) ----
        {
            const char* sKh = (const char*)(baseKh + (size_t)k0 * DKK);
            const char* sKl = (const char*)(baseKl + (size_t)k0 * DKK);
            const char* sVh = (const char*)(baseVh + (size_t)k0 * DKK);
            const char* sVl = (const char*)(baseVl + (size_t)k0 * DKK);
            #pragma unroll
            for (int i = 0; i < 4; i++) {
                int chunk = tg + i * 128;
                int row = chunk >> 3, u = chunk & 7;
                u32 doff = (u32)(row * 128 + ((u ^ (row & 7)) << 4));
                int soff = row * 128 + u * 16;
                cpa16(KhB + doff, sKh + soff);
                cpa16(KlB + doff, sKl + soff);
                cpa16(VhB + doff, sVh + soff);
                cpa16(VlB + doff, sVl + soff);
            }
        }
        asm volatile("cp.async.commit_group;" ::: "memory");
        asm volatile("cp.async.wait_group 0;" ::: "memory");
        asm volatile("bar.sync %0, 128;" :: "r"(1 + g) : "memory");

        const u64 m0 = mr0[it * 2 + g];
        const u64 m1 = mr1[it * 2 + g];

        // ---- fused per-16-key chunk: S -> softmax -> PV ----
        #pragma unroll
        for (int tt = 0; tt < 4; tt++) {
            float s0a[4] = {0.f, 0.f, 0.f, 0.f};
            float s1a[4] = {0.f, 0.f, 0.f, 0.f};
            float s0b[4] = {0.f, 0.f, 0.f, 0.f};
            float s1b[4] = {0.f, 0.f, 0.f, 0.f};
            #pragma unroll
            for (int kc = 0; kc < 4; kc++) {
                float* s0 = (kc < 2) ? s0a : s0b;
                float* s1 = (kc < 2) ? s1a : s1b;
                u32 a0, a1, a2, a3, c0, c1, c2, c3;
                u32 ad = (u32)(tt * 2048) + swzS[kc];
                ldsm4(a0, a1, a2, a3, KhB + ad);
                ldsm4(c0, c1, c2, c3, KlB + ad);
                MMA(s0, qh[kc], a0, a1);
                MMA(s0, qh[kc], c0, c1);
                MMA(s0, ql[kc], a0, a1);
                MMA(s1, qh[kc], a2, a3);
                MMA(s1, qh[kc], c2, c3);
                MMA(s1, ql[kc], a2, a3);
            }
            float s0[4], s1[4];
            #pragma unroll
            for (int j = 0; j < 4; j++) { s0[j] = s0a[j] + s0b[j]; s1[j] = s1a[j] + s1b[j]; }

            const int pos0 = tt * 16 + q4 * 2;
            float p00 = ((m0 >> pos0)        & 1) ? ex2f(s0[0]) : 0.f;
            float p01 = ((m0 >> (pos0 + 1))  & 1) ? ex2f(s0[1]) : 0.f;
            float p02 = ((m1 >> pos0)        & 1) ? ex2f(s0[2]) : 0.f;
            float p03 = ((m1 >> (pos0 + 1))  & 1) ? ex2f(s0[3]) : 0.f;
            float p10 = ((m0 >> (pos0 + 8))  & 1) ? ex2f(s1[0]) : 0.f;
            float p11 = ((m0 >> (pos0 + 9))  & 1) ? ex2f(s1[1]) : 0.f;
            float p12 = ((m1 >> (pos0 + 8))  & 1) ? ex2f(s1[2]) : 0.f;
            float p13 = ((m1 >> (pos0 + 9))  & 1) ? ex2f(s1[3]) : 0.f;
            l0 += (p00 + p01) + (p10 + p11);
            l1 += (p02 + p03) + (p12 + p13);

            u32 ah[4], al[4];
            split2(p00, p01, ah[0], al[0]);
            split2(p02, p03, ah[1], al[1]);
            split2(p10, p11, ah[2], al[2]);
            split2(p12, p13, ah[3], al[3]);

            #pragma unroll
            for (int ntp = 0; ntp < 4; ntp++) {
                u32 h0, h1, h2, h3, e0, e1, e2, e3;
                u32 ad = (u32)(tt * 2048) + swzV[ntp];
                ldsm4t(h0, h1, h2, h3, VhB + ad);
                ldsm4t(e0, e1, e2, e3, VlB + ad);
                MMA(o[2*ntp],     ah, h0, h1);
                MMA(o[2*ntp],     ah, e0, e1);
                MMA(o[2*ntp],     al, h0, h1);
                MMA(o[2*ntp + 1], ah, h2, h3);
                MMA(o[2*ntp + 1], ah, e2, e3);
                MMA(o[2*ntp + 1], al, h2, h3);
            }
        }
        asm volatile("bar.sync %0, 128;" :: "r"(1 + g) : "memory");
    }

    // ---- combine: group 1 stores partials, group 0 adds ----
    float* xch = (float*)((char*)dynsmem + STAGE_B);   // buffer 1, now free
    if (g == 1) {
        float* dst = xch + tg * 35;
        #pragma unroll
        for (int nt = 0; nt < 8; nt++)
            #pragma unroll
            for (int j = 0; j < 4; j++) dst[nt * 4 + j] = o[nt][j];
        dst[32] = l0;
        dst[33] = l1;
    }
    __syncthreads();
    if (g == 1) return;

    {
        const float* src = xch + tg * 35;
        #pragma unroll
        for (int nt = 0; nt < 8; nt++)
            #pragma unroll
            for (int j = 0; j < 4; j++) o[nt][j] += src[nt * 4 + j];
        l0 += src[32];
        l1 += src[33];
    }

    l0 += __shfl_xor_sync(0xffffffffu, l0, 1);
    l0 += __shfl_xor_sync(0xffffffffu, l0, 2);
    l1 += __shfl_xor_sync(0xffffffffu, l1, 1);
    l1 += __shfl_xor_sync(0xffffffffu, l1, 2);
    float inv0 = 1.f / l0, inv1 = 1.f / l1;

    #pragma unroll
    for (int nt = 0; nt < 8; nt++) {
        int d = h * DKK + nt * 8 + q4 * 2;
        u32 hi, lo;
        split2(o[nt][0] * inv0, o[nt][1] * inv0, hi, lo);
        size_t a0 = ((size_t)(b * NN) + r0) * EE + d;
        *(u32*)&g_Ch[a0] = hi; *(u32*)&g_Cl[a0] = lo;
        split2(o[nt][2] * inv1, o[nt][3] * inv1, hi, lo);
        size_t a1 = ((size_t)(b * NN) + r0 + 8) * EE + d;
        *(u32*)&g_Ch[a1] = hi; *(u32*)&g_Cl[a1] = lo;
    }
}

// ---------------------------------------------------------------------------
// Tensor-core output projection (unchanged from R9).
// ---------------------------------------------------------------------------
__global__ void __launch_bounds__(128) out_mma_kernel(
    const float* __restrict__ bo, float* __restrict__ out)
{
    __shared__ __nv_bfloat16 Ah[64*KPAD], Al[64*KPAD];
    __shared__ __nv_bfloat16 Bh[64*KPAD], Bl[64*KPAD];

    const int t = threadIdx.x;
    const int w = t >> 5, lane = t & 31;
    const int gq = lane >> 2, q4 = lane & 3;
    const int m0 = blockIdx.x * 64;
    const int n0 = blockIdx.y * 64;

    float acc[8][4];
    #pragma unroll
    for (int nt = 0; nt < 8; nt++)
        #pragma unroll
        for (int j = 0; j < 4; j++) acc[nt][j] = 0.f;

    const u32 AhB = sptr(Ah), AlB = sptr(Al), BhB = sptr(Bh), BlB = sptr(Bl);
    const u32 offA = (u32)(((lane & 7) + (((lane >> 3) & 1) << 3) + w * 16) * (KPAD * 2)
                           + (((lane >> 4) & 1) << 4));
    const u32 offB = (u32)(((lane & 7) + (((lane >> 4) & 1) << 3)) * (KPAD * 2)
                           + (((lane >> 3) & 1) << 4));

    for (int k0 = 0; k0 < EE; k0 += 64) {
        __syncthreads();
        #pragma unroll
        for (int i8 = t * 8; i8 < 64 * 64; i8 += 128 * 8) {
            int row = i8 >> 6, col = i8 & 63;
            int so = row * KPAD + col;
            *(float4*)&Ah[so] = *(const float4*)&g_Ch[(size_t)(m0 + row) * EE + k0 + col];
            *(float4*)&Al[so] = *(const float4*)&g_Cl[(size_t)(m0 + row) * EE + k0 + col];
            *(float4*)&Bh[so] = *(const float4*)&g_Woh[(size_t)(n0 + row) * EE + k0 + col];
            *(float4*)&Bl[so] = *(const float4*)&g_Wol[(size_t)(n0 + row) * EE + k0 + col];
        }
        __syncthreads();

        #pragma unroll
        for (int k16 = 0; k16 < 4; k16++) {
            u32 ah[4], al[4];
            ldsm4(ah[0], ah[1], ah[2], ah[3], AhB + offA + k16 * 32);
            ldsm4(al[0], al[1], al[2], al[3], AlB + offA + k16 * 32);
            #pragma unroll
            for (int ntp = 0; ntp < 4; ntp++) {
                u32 b0, b1, b2, b3, c0, c1, c2, c3;
                u32 ad = offB + (u32)(ntp * 16 * KPAD * 2 + k16 * 32);
                ldsm4(b0, b1, b2, b3, BhB + ad);
                ldsm4(c0, c1, c2, c3, BlB + ad);
                MMA(acc[2*ntp],     ah, b0, b1);
                MMA(acc[2*ntp],     ah, c0, c1);
                MMA(acc[2*ntp],     al, b0, b1);
                MMA(acc[2*ntp + 1], ah, b2, b3);
                MMA(acc[2*ntp + 1], ah, c2, c3);
                MMA(acc[2*ntp + 1], al, b2, b3);
            }
        }
    }

    const int r0 = m0 + w * 16 + gq;
    #pragma unroll
    for (int nt = 0; nt < 8; nt++) {
        int c = n0 + nt * 8 + q4 * 2;
        float2 bv = *(const float2*)&bo[c];
        float2 v0 = make_float2(acc[nt][0] + bv.x, acc[nt][1] + bv.y);
        float2 v1 = make_float2(acc[nt][2] + bv.x, acc[nt][3] + bv.y);
        *(float2*)&out[(size_t)(r0    ) * EE + c] = v0;
        *(float2*)&out[(size_t)(r0 + 8) * EE + c] = v1;
    }
}

// ---------------------------------------------------------------------------
extern "C" void kernel_launch(void* const* d_in, const int* in_sizes, int n_in,
                              void* d_out, int out_size)
{
    const float* X   = (const float*)d_in[0];
    const int*   Adj = (const int*)  d_in[1];
    const float* Wq  = (const float*)d_in[2];
    const float* Wk  = (const float*)d_in[3];
    const float* Wv  = (const float*)d_in[4];
    const float* Wo  = (const float*)d_in[5];
    const float* bo  = (const float*)d_in[6];
    float* out = (float*)d_out;

    cudaFuncSetAttribute(attn_kernel,
        cudaFuncAttributeMaxDynamicSharedMemorySize, 2 * STAGE_B);

    prep_kernel<<<34816, 256>>>(Adj, X, Wq, Wk, Wv, Wo);
    qkv_mma_kernel<<<dim3(MTOT/64, 12), 128>>>();
    attn_kernel<<<dim3(NN/64, BB*HH), 256, 2*STAGE_B>>>();
    out_mma_kernel<<<dim3(MTOT/64, 4), 128>>>(bo, out);
}

// round 12
// speedup vs baseline: 1.1621x; 1.0177x over previous
#include <cuda_runtime.h>
#include <cuda_bf16.h>
#include <math.h>
#include <stdint.h>
#include <stddef.h>

#define BB 2
#define NN 2048
#define EE 256
#define HH 4
#define DKK 64
#define MTOT (BB*NN)

// 1/sqrt(64) * log2(e): scores produced in log2 domain for ex2-softmax
#define QSCALE 0.1803368801111204f

typedef unsigned int u32;
typedef unsigned long long u64;

__device__ __forceinline__ float ex2f(float x) {
    float r; asm("ex2.approx.f32 %0, %1;" : "=f"(r) : "f"(x)); return r;
}
__device__ __forceinline__ u32 sptr(const void* p) {
    return (u32)__cvta_generic_to_shared(p);
}
__device__ __forceinline__ void ldsm4(u32& r0, u32& r1, u32& r2, u32& r3, u32 a) {
    asm volatile("ldmatrix.sync.aligned.m8n8.x4.shared.b16 {%0,%1,%2,%3}, [%4];"
        : "=r"(r0), "=r"(r1), "=r"(r2), "=r"(r3) : "r"(a));
}
__device__ __forceinline__ void ldsm4t(u32& r0, u32& r1, u32& r2, u32& r3, u32 a) {
    asm volatile("ldmatrix.sync.aligned.m8n8.x4.trans.shared.b16 {%0,%1,%2,%3}, [%4];"
        : "=r"(r0), "=r"(r1), "=r"(r2), "=r"(r3) : "r"(a));
}
__device__ __forceinline__ void cpa16(u32 dst, const void* src) {
    asm volatile("cp.async.cg.shared.global [%0], [%1], 16;" :: "r"(dst), "l"(src));
}
#define CP_COMMIT() asm volatile("cp.async.commit_group;" ::: "memory")
#define CP_WAIT(n)  asm volatile("cp.async.wait_group %0;" :: "n"(n) : "memory")

// Scratch: everything the hot kernels touch is pre-split bf16 hi/lo.
__device__ __align__(16) __nv_bfloat16 g_Xh[MTOT*EE],  g_Xl[MTOT*EE];
__device__ __align__(16) __nv_bfloat16 g_Wh[12*DKK*EE], g_Wl[12*DKK*EE];
__device__ __align__(16) __nv_bfloat16 g_Woh[EE*EE],   g_Wol[EE*EE];
__device__ __align__(16) __nv_bfloat16 g_Qh[BB*HH*NN*DKK], g_Ql[BB*HH*NN*DKK];
__device__ __align__(16) __nv_bfloat16 g_Kh[BB*HH*NN*DKK], g_Kl[BB*HH*NN*DKK];
__device__ __align__(16) __nv_bfloat16 g_Vh[BB*HH*NN*DKK], g_Vl[BB*HH*NN*DKK];
__device__ __align__(16) __nv_bfloat16 g_Ch[MTOT*EE],  g_Cl[MTOT*EE];
__device__ u32 g_mask[BB*NN*NN/32];

// fast bf16 hi/lo split of a float pair
__device__ __forceinline__ void split2(float x, float y, u32& hi, u32& lo) {
    asm("cvt.rn.bf16x2.f32 %0, %1, %2;" : "=r"(hi) : "f"(y), "f"(x));
    float hx = __uint_as_float(hi << 16);
    float hy = __uint_as_float(hi & 0xffff0000u);
    float rx = x - hx, ry = y - hy;
    asm("cvt.rn.bf16x2.f32 %0, %1, %2;" : "=r"(lo) : "f"(ry), "f"(rx));
}

#define MMA(d, a, b0_, b1_) asm volatile( \
    "mma.sync.aligned.m16n8k16.row.col.f32.bf16.bf16.f32 " \
    "{%0,%1,%2,%3}, {%4,%5,%6,%7}, {%8,%9}, {%0,%1,%2,%3};" \
    : "+f"(d[0]), "+f"(d[1]), "+f"(d[2]), "+f"(d[3]) \
    : "r"(a[0]), "r"(a[1]), "r"(a[2]), "r"(a[3]), "r"(b0_), "r"(b1_))

extern __shared__ __nv_bfloat16 dynsmem[];

// ---------------------------------------------------------------------------
// Merged prep (unchanged).
// ---------------------------------------------------------------------------
__global__ void __launch_bounds__(256) prep_kernel(
    const int* __restrict__ Adj, const float* __restrict__ X,
    const float* __restrict__ Wq, const float* __restrict__ Wk,
    const float* __restrict__ Wv, const float* __restrict__ Wo)
{
    const int bid = blockIdx.x;
    const int t = threadIdx.x;

    if (bid < 32768) {
        int gid  = bid * 256 + t;
        int word = gid >> 5, lane = gid & 31;
        int v = Adj[(size_t)word * 32 + lane];
        u32 m = __ballot_sync(0xffffffffu, v > 0);
        if (lane == 0) g_mask[word] = m;
    } else if (bid < 33792) {
        int i = ((bid - 32768) * 256 + t) * 4;
        float4 v = *(const float4*)&X[i];
        u32 h0, l0, h1, l1;
        split2(v.x, v.y, h0, l0);
        split2(v.z, v.w, h1, l1);
        *(u32*)&g_Xh[i]     = h0; *(u32*)&g_Xh[i + 2] = h1;
        *(u32*)&g_Xl[i]     = l0; *(u32*)&g_Xl[i + 2] = l1;
    } else if (bid < 34560) {
        int idx = (bid - 33792) * 256 + t;
        int mat = idx >> 16;
        int rem = idx & 65535;
        const float* src = (mat == 0) ? Wq : (mat == 1) ? Wk : Wv;
        int h = rem >> 14, d = (rem >> 6) & 255, e = rem & 63;
        float v = src[rem];
        __nv_bfloat16 hi = __float2bfloat16(v);
        size_t dst = (size_t)((mat * HH + h) * DKK + e) * EE + d;
        g_Wh[dst] = hi;
        g_Wl[dst] = __float2bfloat16(v - __bfloat162float(hi));
    } else {
        int idx = (bid - 34560) * 256 + t;
        float v = Wo[idx];
        __nv_bfloat16 hi = __float2bfloat16(v);
        g_Woh[idx] = hi;
        g_Wol[idx] = __float2bfloat16(v - __bfloat162float(hi));
    }
}

// ---------------------------------------------------------------------------
// Shared GEMM mainloop pieces (64x64 output tile, K=256, 256 thr = 8 warps,
// warp = 16 rows x 32 cols; cp.async double-buffered swizzled smem).
// ---------------------------------------------------------------------------
#define GSTAGE 32768

#define GEMM_FILL(st, k0, sAh, sAl, sBh, sBl) do { \
    u32 dB = base + (st) * GSTAGE; \
    int kbyte = (k0) * 2; \
    _Pragma("unroll") \
    for (int i_ = 0; i_ < 2; i_++) { \
        int chunk = t + i_ * 256; \
        int row = chunk >> 3, u = chunk & 7; \
        u32 doff = (u32)(row * 128 + ((u ^ (row & 7)) << 4)); \
        int soff = row * 512 + kbyte + u * 16; \
        cpa16(dB +         doff, (sAh) + soff); \
        cpa16(dB +  8192 + doff, (sAl) + soff); \
        cpa16(dB + 16384 + doff, (sBh) + soff); \
        cpa16(dB + 24576 + doff, (sBl) + soff); \
    } \
} while (0)

#define GEMM_COMPUTE(st) do { \
    u32 stB = base + (st) * GSTAGE; \
    u32 AhB = stB, AlB = stB + 8192, BhB = stB + 16384, BlB = stB + 24576; \
    _Pragma("unroll") \
    for (int k16 = 0; k16 < 4; k16++) { \
        u32 adA = (u32)(rowA * 128 + (((k16 * 2 + uA) ^ la7) << 4)); \
        u32 ah[4], al[4]; \
        ldsm4(ah[0], ah[1], ah[2], ah[3], AhB + adA); \
        ldsm4(al[0], al[1], al[2], al[3], AlB + adA); \
        _Pragma("unroll") \
        for (int ntp = 0; ntp < 2; ntp++) { \
            int rowB = cw * 32 + ntp * 16 + rowBb; \
            u32 adB = (u32)(rowB * 128 + (((k16 * 2 + uB) ^ la7) << 4)); \
            u32 b0, b1, b2, b3, c0, c1, c2, c3; \
            ldsm4(b0, b1, b2, b3, BhB + adB); \
            ldsm4(c0, c1, c2, c3, BlB + adB); \
            MMA(acc[2*ntp],     ah, b0, b1); \
            MMA(acc[2*ntp],     ah, c0, c1); \
            MMA(acc[2*ntp],     al, b0, b1); \
            MMA(acc[2*ntp + 1], ah, b2, b3); \
            MMA(acc[2*ntp + 1], ah, c2, c3); \
            MMA(acc[2*ntp + 1], al, b2, b3); \
        } \
    } \
} while (0)

#define GEMM_PRELUDE() \
    const int t = threadIdx.x; \
    const int w = t >> 5, lane = t & 31; \
    const int rw = w & 3, cw = w >> 2; \
    const int gq = lane >> 2, q4 = lane & 3; \
    const int la7 = lane & 7; \
    const int rowA = rw * 16 + la7 + (((lane >> 3) & 1) << 3); \
    const int uA = (lane >> 4) & 1; \
    const int rowBb = la7 + (((lane >> 4) & 1) << 3); \
    const int uB = (lane >> 3) & 1; \
    const u32 base = sptr(dynsmem); \
    float acc[4][4]; \
    _Pragma("unroll") \
    for (int nt_ = 0; nt_ < 4; nt_++) \
        _Pragma("unroll") \
        for (int j_ = 0; j_ < 4; j_++) acc[nt_][j_] = 0.f;

#define GEMM_LOOP(sAh, sAl, sBh, sBl) \
    GEMM_FILL(0, 0, sAh, sAl, sBh, sBl); \
    CP_COMMIT(); \
    for (int kb = 0; kb < 4; kb++) { \
        int st = kb & 1; \
        if (kb < 3) { GEMM_FILL(st ^ 1, (kb + 1) * 64, sAh, sAl, sBh, sBl); CP_COMMIT(); CP_WAIT(1); } \
        else CP_WAIT(0); \
        __syncthreads(); \
        GEMM_COMPUTE(st); \
        __syncthreads(); \
    }

// ---------------------------------------------------------------------------
// QKV projection. Grid (64, 12): y = mat*4 + h.
// ---------------------------------------------------------------------------
__global__ void __launch_bounds__(256) qkv_mma_kernel()
{
    GEMM_PRELUDE();
    const int m0 = blockIdx.x * 64;
    const int n0 = blockIdx.y * 64;

    const char* sAh = (const char*)(g_Xh + (size_t)m0 * EE);
    const char* sAl = (const char*)(g_Xl + (size_t)m0 * EE);
    const char* sBh = (const char*)(g_Wh + (size_t)n0 * EE);
    const char* sBl = (const char*)(g_Wl + (size_t)n0 * EE);

    GEMM_LOOP(sAh, sAl, sBh, sBl);

    const int mat = n0 >> 8, h = (n0 >> 6) & 3;
    __nv_bfloat16* dh = (mat == 0) ? g_Qh : (mat == 1) ? g_Kh : g_Vh;
    __nv_bfloat16* dl = (mat == 0) ? g_Ql : (mat == 1) ? g_Kl : g_Vl;
    const float mult = (mat == 0) ? QSCALE : 1.0f;

    const int r0 = m0 + rw * 16 + gq;
    const int b0_ = r0 >> 11, n2_0 = r0 & 2047;
    const int b1_ = (r0 + 8) >> 11, n2_1 = (r0 + 8) & 2047;
    #pragma unroll
    for (int nt = 0; nt < 4; nt++) {
        int c = cw * 32 + nt * 8 + q4 * 2;
        u32 hi, lo;
        split2(acc[nt][0] * mult, acc[nt][1] * mult, hi, lo);
        size_t a0 = ((size_t)((b0_ * HH + h) * NN + n2_0)) * DKK + c;
        *(u32*)&dh[a0] = hi; *(u32*)&dl[a0] = lo;
        split2(acc[nt][2] * mult, acc[nt][3] * mult, hi, lo);
        size_t a1 = ((size_t)((b1_ * HH + h) * NN + n2_1)) * DKK + c;
        *(u32*)&dh[a1] = hi; *(u32*)&dl[a1] = lo;
    }
}

// ---------------------------------------------------------------------------
// Output projection. Grid (64, 4).
// ---------------------------------------------------------------------------
__global__ void __launch_bounds__(256) out_mma_kernel(
    const float* __restrict__ bo, float* __restrict__ out)
{
    GEMM_PRELUDE();
    const int m0 = blockIdx.x * 64;
    const int n0 = blockIdx.y * 64;

    const char* sAh = (const char*)(g_Ch + (size_t)m0 * EE);
    const char* sAl = (const char*)(g_Cl + (size_t)m0 * EE);
    const char* sBh = (const char*)(g_Woh + (size_t)n0 * EE);
    const char* sBl = (const char*)(g_Wol + (size_t)n0 * EE);

    GEMM_LOOP(sAh, sAl, sBh, sBl);

    const int r0 = m0 + rw * 16 + gq;
    #pragma unroll
    for (int nt = 0; nt < 4; nt++) {
        int c = n0 + cw * 32 + nt * 8 + q4 * 2;
        float2 bv = *(const float2*)&bo[c];
        float2 v0 = make_float2(acc[nt][0] + bv.x, acc[nt][1] + bv.y);
        float2 v1 = make_float2(acc[nt][2] + bv.x, acc[nt][3] + bv.y);
        *(float2*)&out[(size_t)(r0    ) * EE + c] = v0;
        *(float2*)&out[(size_t)(r0 + 8) * EE + c] = v1;
    }
}

// ---------------------------------------------------------------------------
// Flash attention: split-K warp groups, per-group double-buffered {Kh,Kl,Vh}
// (2 x 24 KB) + single-buffered Vl (8 KB) whose fill hides under the S phase.
// 3-term PV restored (full precision). 56 KB/group, 112 KB/CTA -> 2 CTAs/SM.
// ---------------------------------------------------------------------------
#define ASTAGE 24576
#define AVL_OFF (2*ASTAGE)            // 49152
#define AGROUP (2*ASTAGE + 8192)      // 57344

__global__ void __launch_bounds__(256, 2) attn_kernel()
{
    const int t = threadIdx.x;
    const int w = t >> 5, lane = t & 31;
    const int g = w >> 2;
    const int wg = w & 3;
    const int tg = t & 127;
    const int gq = lane >> 2, q4 = lane & 3;
    const int q0 = blockIdx.x * 64;
    const int bh = blockIdx.y;
    const int b  = bh >> 2, h = bh & 3;

    const int r0 = q0 + wg * 16 + gq;

    // ---- Q fragments ----
    u32 qh[4][4], ql[4][4];
    {
        const __nv_bfloat16* Qh = g_Qh + (size_t)bh * NN * DKK;
        const __nv_bfloat16* Ql = g_Ql + (size_t)bh * NN * DKK;
        #pragma unroll
        for (int kc = 0; kc < 4; kc++) {
            int c = kc * 16 + q4 * 2;
            qh[kc][0] = *(const u32*)&Qh[(size_t)(r0    ) * DKK + c    ];
            qh[kc][1] = *(const u32*)&Qh[(size_t)(r0 + 8) * DKK + c    ];
            qh[kc][2] = *(const u32*)&Qh[(size_t)(r0    ) * DKK + c + 8];
            qh[kc][3] = *(const u32*)&Qh[(size_t)(r0 + 8) * DKK + c + 8];
            ql[kc][0] = *(const u32*)&Ql[(size_t)(r0    ) * DKK + c    ];
            ql[kc][1] = *(const u32*)&Ql[(size_t)(r0 + 8) * DKK + c    ];
            ql[kc][2] = *(const u32*)&Ql[(size_t)(r0    ) * DKK + c + 8];
            ql[kc][3] = *(const u32*)&Ql[(size_t)(r0 + 8) * DKK + c + 8];
        }
    }

    float o[8][4];
    #pragma unroll
    for (int nt = 0; nt < 8; nt++)
        #pragma unroll
        for (int j = 0; j < 4; j++) o[nt][j] = 0.f;
    float l0 = 0.f, l1 = 0.f;

    const u64* mr0 = (const u64*)g_mask + ((size_t)(b * NN + r0    )) * (NN / 64);
    const u64* mr1 = (const u64*)g_mask + ((size_t)(b * NN + r0 + 8)) * (NN / 64);

    const u32 gB = sptr(dynsmem) + g * AGROUP;
    const u32 VlB = gB + AVL_OFF;

    const int rS  = (lane & 7) + ((lane >> 4) << 3);
    const int ubS = (lane >> 3) & 1;
    u32 swzS[4];
    #pragma unroll
    for (int kc = 0; kc < 4; kc++)
        swzS[kc] = (u32)(rS * 128 + (((kc * 2 + ubS) ^ (rS & 7)) << 4));
    const int rV  = (lane & 7) + (((lane >> 3) & 1) << 3);
    const int ubV = (lane >> 4) & 1;
    u32 swzV[4];
    #pragma unroll
    for (int ntp = 0; ntp < 4; ntp++)
        swzV[ntp] = (u32)(rV * 128 + (((ntp * 2 + ubV) ^ (rV & 7)) << 4));

    const __nv_bfloat16* baseKh = g_Kh + (size_t)bh * NN * DKK;
    const __nv_bfloat16* baseKl = g_Kl + (size_t)bh * NN * DKK;
    const __nv_bfloat16* baseVh = g_Vh + (size_t)bh * NN * DKK;
    const __nv_bfloat16* baseVl = g_Vl + (size_t)bh * NN * DKK;

    auto fillKVh = [&](int st, int k0) {
        u32 dB = gB + st * ASTAGE;
        const char* sKh = (const char*)(baseKh + (size_t)k0 * DKK);
        const char* sKl = (const char*)(baseKl + (size_t)k0 * DKK);
        const char* sVh = (const char*)(baseVh + (size_t)k0 * DKK);
        #pragma unroll
        for (int i = 0; i < 4; i++) {
            int chunk = tg + i * 128;
            int row = chunk >> 3, u = chunk & 7;
            u32 doff = (u32)(row * 128 + ((u ^ (row & 7)) << 4));
            int soff = row * 128 + u * 16;
            cpa16(dB +         doff, sKh + soff);
            cpa16(dB +  8192 + doff, sKl + soff);
            cpa16(dB + 16384 + doff, sVh + soff);
        }
    };
    auto fillVl = [&](int k0) {
        const char* sVl = (const char*)(baseVl + (size_t)k0 * DKK);
        #pragma unroll
        for (int i = 0; i < 4; i++) {
            int chunk = tg + i * 128;
            int row = chunk >> 3, u = chunk & 7;
            u32 doff = (u32)(row * 128 + ((u ^ (row & 7)) << 4));
            int soff = row * 128 + u * 16;
            cpa16(VlB + doff, sVl + soff);
        }
    };

    fillKVh(0, g * 64);
    CP_COMMIT();

    for (int it = 0; it < 16; it++) {
        const int st = it & 1;
        const int k0 = it * 128 + g * 64;

        fillVl(k0);
        CP_COMMIT();
        if (it < 15) {
            fillKVh(st ^ 1, k0 + 128);
            CP_COMMIT();
            CP_WAIT(2);            // KVh(it) complete
        } else {
            CP_WAIT(1);
        }
        asm volatile("bar.sync %0, 128;" :: "r"(1 + g) : "memory");

        const u32 stB = gB + st * ASTAGE;
        const u32 KhB = stB, KlB = stB + 8192, VhB = stB + 16384;

        const u64 m0 = mr0[it * 2 + g];
        const u64 m1 = mr1[it * 2 + g];

        #pragma unroll
        for (int tt = 0; tt < 4; tt++) {
            float s0a[4] = {0.f, 0.f, 0.f, 0.f};
            float s1a[4] = {0.f, 0.f, 0.f, 0.f};
            float s0b[4] = {0.f, 0.f, 0.f, 0.f};
            float s1b[4] = {0.f, 0.f, 0.f, 0.f};
            #pragma unroll
            for (int kc = 0; kc < 4; kc++) {
                float* s0 = (kc < 2) ? s0a : s0b;
                float* s1 = (kc < 2) ? s1a : s1b;
                u32 a0, a1, a2, a3, c0, c1, c2, c3;
                u32 ad = (u32)(tt * 2048) + swzS[kc];
                ldsm4(a0, a1, a2, a3, KhB + ad);
                ldsm4(c0, c1, c2, c3, KlB + ad);
                MMA(s0, qh[kc], a0, a1);
                MMA(s0, qh[kc], c0, c1);
                MMA(s0, ql[kc], a0, a1);
                MMA(s1, qh[kc], a2, a3);
                MMA(s1, qh[kc], c2, c3);
                MMA(s1, ql[kc], a2, a3);
            }
            float s0[4], s1[4];
            #pragma unroll
            for (int j = 0; j < 4; j++) { s0[j] = s0a[j] + s0b[j]; s1[j] = s1a[j] + s1b[j]; }

            const int pos0 = tt * 16 + q4 * 2;
            float p00 = ((m0 >> pos0)        & 1) ? ex2f(s0[0]) : 0.f;
            float p01 = ((m0 >> (pos0 + 1))  & 1) ? ex2f(s0[1]) : 0.f;
            float p02 = ((m1 >> pos0)        & 1) ? ex2f(s0[2]) : 0.f;
            float p03 = ((m1 >> (pos0 + 1))  & 1) ? ex2f(s0[3]) : 0.f;
            float p10 = ((m0 >> (pos0 + 8))  & 1) ? ex2f(s1[0]) : 0.f;
            float p11 = ((m0 >> (pos0 + 9))  & 1) ? ex2f(s1[1]) : 0.f;
            float p12 = ((m1 >> (pos0 + 8))  & 1) ? ex2f(s1[2]) : 0.f;
            float p13 = ((m1 >> (pos0 + 9))  & 1) ? ex2f(s1[3]) : 0.f;
            l0 += (p00 + p01) + (p10 + p11);
            l1 += (p02 + p03) + (p12 + p13);

            u32 ah[4], al[4];
            split2(p00, p01, ah[0], al[0]);
            split2(p02, p03, ah[1], al[1]);
            split2(p10, p11, ah[2], al[2]);
            split2(p12, p13, ah[3], al[3]);

            if (tt == 0) {
                // Vl(it) fill has been in flight behind the S chunk above
                if (it < 15) CP_WAIT(1); else CP_WAIT(0);
                asm volatile("bar.sync %0, 128;" :: "r"(1 + g) : "memory");
            }

            #pragma unroll
            for (int ntp = 0; ntp < 4; ntp++) {
                u32 h0, h1, h2, h3, e0, e1, e2, e3;
                u32 ad = (u32)(tt * 2048) + swzV[ntp];
                ldsm4t(h0, h1, h2, h3, VhB + ad);
                ldsm4t(e0, e1, e2, e3, VlB + ad);
                MMA(o[2*ntp],     ah, h0, h1);
                MMA(o[2*ntp],     ah, e0, e1);
                MMA(o[2*ntp],     al, h0, h1);
                MMA(o[2*ntp + 1], ah, h2, h3);
                MMA(o[2*ntp + 1], ah, e2, e3);
                MMA(o[2*ntp + 1], al, h2, h3);
            }
        }
        asm volatile("bar.sync %0, 128;" :: "r"(1 + g) : "memory");
    }

    // ---- combine: group 1 stores partials into its (now free) region ----
    float* xch = (float*)((char*)dynsmem + AGROUP);
    if (g == 1) {
        float* dst = xch + tg * 35;
        #pragma unroll
        for (int nt = 0; nt < 8; nt++)
            #pragma unroll
            for (int j = 0; j < 4; j++) dst[nt * 4 + j] = o[nt][j];
        dst[32] = l0;
        dst[33] = l1;
    }
    __syncthreads();
    if (g == 1) return;

    {
        const float* src = xch + tg * 35;
        #pragma unroll
        for (int nt = 0; nt < 8; nt++)
            #pragma unroll
            for (int j = 0; j < 4; j++) o[nt][j] += src[nt * 4 + j];
        l0 += src[32];
        l1 += src[33];
    }

    l0 += __shfl_xor_sync(0xffffffffu, l0, 1);
    l0 += __shfl_xor_sync(0xffffffffu, l0, 2);
    l1 += __shfl_xor_sync(0xffffffffu, l1, 1);
    l1 += __shfl_xor_sync(0xffffffffu, l1, 2);
    float inv0 = 1.f / l0, inv1 = 1.f / l1;

    #pragma unroll
    for (int nt = 0; nt < 8; nt++) {
        int d = h * DKK + nt * 8 + q4 * 2;
        u32 hi, lo;
        split2(o[nt][0] * inv0, o[nt][1] * inv0, hi, lo);
        size_t a0 = ((size_t)(b * NN) + r0) * EE + d;
        *(u32*)&g_Ch[a0] = hi; *(u32*)&g_Cl[a0] = lo;
        split2(o[nt][2] * inv1, o[nt][3] * inv1, hi, lo);
        size_t a1 = ((size_t)(b * NN) + r0 + 8) * EE + d;
        *(u32*)&g_Ch[a1] = hi; *(u32*)&g_Cl[a1] = lo;
    }
}

// ---------------------------------------------------------------------------
extern "C" void kernel_launch(void* const* d_in, const int* in_sizes, int n_in,
                              void* d_out, int out_size)
{
    const float* X   = (const float*)d_in[0];
    const int*   Adj = (const int*)  d_in[1];
    const float* Wq  = (const float*)d_in[2];
    const float* Wk  = (const float*)d_in[3];
    const float* Wv  = (const float*)d_in[4];
    const float* Wo  = (const float*)d_in[5];
    const float* bo  = (const float*)d_in[6];
    float* out = (float*)d_out;

    cudaFuncSetAttribute(attn_kernel,
        cudaFuncAttributeMaxDynamicSharedMemorySize, 2 * AGROUP);
    cudaFuncSetAttribute(qkv_mma_kernel,
        cudaFuncAttributeMaxDynamicSharedMemorySize, 2 * GSTAGE);
    cudaFuncSetAttribute(out_mma_kernel,
        cudaFuncAttributeMaxDynamicSharedMemorySize, 2 * GSTAGE);

    prep_kernel<<<34816, 256>>>(Adj, X, Wq, Wk, Wv, Wo);
    qkv_mma_kernel<<<dim3(MTOT/64, 12), 256, 2*GSTAGE>>>();
    attn_kernel<<<dim3(NN/64, BB*HH), 256, 2*AGROUP>>>();
    out_mma_kernel<<<dim3(MTOT/64, 4), 256, 2*GSTAGE>>>(bo, out);
}

// round 13
// speedup vs baseline: 1.6039x; 1.3802x over previous
#include <cuda_runtime.h>
#include <cuda_bf16.h>
#include <cuda_fp16.h>
#include <math.h>
#include <stdint.h>
#include <stddef.h>

#define BB 2
#define NN 2048
#define EE 256
#define HH 4
#define DKK 64
#define MTOT (BB*NN)

// 1/sqrt(64) * log2(e): scores produced in log2 domain for ex2-softmax
#define QSCALE 0.1803368801111204f

typedef unsigned int u32;
typedef unsigned long long u64;

__device__ __forceinline__ float ex2f(float x) {
    float r; asm("ex2.approx.f32 %0, %1;" : "=f"(r) : "f"(x)); return r;
}
__device__ __forceinline__ u32 sptr(const void* p) {
    return (u32)__cvta_generic_to_shared(p);
}
__device__ __forceinline__ void ldsm4(u32& r0, u32& r1, u32& r2, u32& r3, u32 a) {
    asm volatile("ldmatrix.sync.aligned.m8n8.x4.shared.b16 {%0,%1,%2,%3}, [%4];"
        : "=r"(r0), "=r"(r1), "=r"(r2), "=r"(r3) : "r"(a));
}
__device__ __forceinline__ void ldsm4t(u32& r0, u32& r1, u32& r2, u32& r3, u32 a) {
    asm volatile("ldmatrix.sync.aligned.m8n8.x4.trans.shared.b16 {%0,%1,%2,%3}, [%4];"
        : "=r"(r0), "=r"(r1), "=r"(r2), "=r"(r3) : "r"(a));
}
__device__ __forceinline__ void cpa16(u32 dst, const void* src) {
    asm volatile("cp.async.cg.shared.global [%0], [%1], 16;" :: "r"(dst), "l"(src));
}
#define CP_COMMIT() asm volatile("cp.async.commit_group;" ::: "memory")
#define CP_WAIT(n)  asm volatile("cp.async.wait_group %0;" :: "n"(n) : "memory")

// Scratch.
__device__ __align__(16) __nv_bfloat16 g_Xh[MTOT*EE],  g_Xl[MTOT*EE];
__device__ __align__(16) __nv_bfloat16 g_Wh[12*DKK*EE], g_Wl[12*DKK*EE];
__device__ __align__(16) __nv_bfloat16 g_Woh[EE*EE],   g_Wol[EE*EE];
__device__ __align__(16) __half g_Qh[BB*HH*NN*DKK], g_Ql[BB*HH*NN*DKK];
__device__ __align__(16) __half g_K [BB*HH*NN*DKK];
__device__ __align__(16) __half g_V [BB*HH*NN*DKK];
__device__ __align__(16) __nv_bfloat16 g_Ch[MTOT*EE],  g_Cl[MTOT*EE];
__device__ u32 g_mask[BB*NN*NN/32];

// bf16 hi/lo split of a float pair (projections)
__device__ __forceinline__ void split2(float x, float y, u32& hi, u32& lo) {
    asm("cvt.rn.bf16x2.f32 %0, %1, %2;" : "=r"(hi) : "f"(y), "f"(x));
    float hx = __uint_as_float(hi << 16);
    float hy = __uint_as_float(hi & 0xffff0000u);
    float rx = x - hx, ry = y - hy;
    asm("cvt.rn.bf16x2.f32 %0, %1, %2;" : "=r"(lo) : "f"(ry), "f"(rx));
}
// fp16 pack of a float pair
__device__ __forceinline__ u32 pack2h(float x, float y) {
    u32 r; asm("cvt.rn.f16x2.f32 %0, %1, %2;" : "=r"(r) : "f"(y), "f"(x)); return r;
}
// fp16 hi/lo split of a float pair (Q)
__device__ __forceinline__ void split2h(float x, float y, u32& hi, u32& lo) {
    hi = pack2h(x, y);
    __half2 hh = *(__half2*)&hi;
    float rx = x - __low2float(hh), ry = y - __high2float(hh);
    lo = pack2h(rx, ry);
}

#define MMA(d, a, b0_, b1_) asm volatile( \
    "mma.sync.aligned.m16n8k16.row.col.f32.bf16.bf16.f32 " \
    "{%0,%1,%2,%3}, {%4,%5,%6,%7}, {%8,%9}, {%0,%1,%2,%3};" \
    : "+f"(d[0]), "+f"(d[1]), "+f"(d[2]), "+f"(d[3]) \
    : "r"(a[0]), "r"(a[1]), "r"(a[2]), "r"(a[3]), "r"(b0_), "r"(b1_))

#define MMAH(d, a, b0_, b1_) asm volatile( \
    "mma.sync.aligned.m16n8k16.row.col.f32.f16.f16.f32 " \
    "{%0,%1,%2,%3}, {%4,%5,%6,%7}, {%8,%9}, {%0,%1,%2,%3};" \
    : "+f"(d[0]), "+f"(d[1]), "+f"(d[2]), "+f"(d[3]) \
    : "r"(a[0]), "r"(a[1]), "r"(a[2]), "r"(a[3]), "r"(b0_), "r"(b1_))

extern __shared__ __nv_bfloat16 dynsmem[];

// ---------------------------------------------------------------------------
// Merged prep (unchanged).
// ---------------------------------------------------------------------------
__global__ void __launch_bounds__(256) prep_kernel(
    const int* __restrict__ Adj, const float* __restrict__ X,
    const float* __restrict__ Wq, const float* __restrict__ Wk,
    const float* __restrict__ Wv, const float* __restrict__ Wo)
{
    const int bid = blockIdx.x;
    const int t = threadIdx.x;

    if (bid < 32768) {
        int gid  = bid * 256 + t;
        int word = gid >> 5, lane = gid & 31;
        int v = Adj[(size_t)word * 32 + lane];
        u32 m = __ballot_sync(0xffffffffu, v > 0);
        if (lane == 0) g_mask[word] = m;
    } else if (bid < 33792) {
        int i = ((bid - 32768) * 256 + t) * 4;
        float4 v = *(const float4*)&X[i];
        u32 h0, l0, h1, l1;
        split2(v.x, v.y, h0, l0);
        split2(v.z, v.w, h1, l1);
        *(u32*)&g_Xh[i]     = h0; *(u32*)&g_Xh[i + 2] = h1;
        *(u32*)&g_Xl[i]     = l0; *(u32*)&g_Xl[i + 2] = l1;
    } else if (bid < 34560) {
        int idx = (bid - 33792) * 256 + t;
        int mat = idx >> 16;
        int rem = idx & 65535;
        const float* src = (mat == 0) ? Wq : (mat == 1) ? Wk : Wv;
        int h = rem >> 14, d = (rem >> 6) & 255, e = rem & 63;
        float v = src[rem];
        __nv_bfloat16 hi = __float2bfloat16(v);
        size_t dst = (size_t)((mat * HH + h) * DKK + e) * EE + d;
        g_Wh[dst] = hi;
        g_Wl[dst] = __float2bfloat16(v - __bfloat162float(hi));
    } else {
        int idx = (bid - 34560) * 256 + t;
        float v = Wo[idx];
        __nv_bfloat16 hi = __float2bfloat16(v);
        g_Woh[idx] = hi;
        g_Wol[idx] = __float2bfloat16(v - __bfloat162float(hi));
    }
}

// ---------------------------------------------------------------------------
// Shared GEMM mainloop pieces (unchanged from R12).
// ---------------------------------------------------------------------------
#define GSTAGE 32768

#define GEMM_FILL(st, k0, sAh, sAl, sBh, sBl) do { \
    u32 dB = base + (st) * GSTAGE; \
    int kbyte = (k0) * 2; \
    _Pragma("unroll") \
    for (int i_ = 0; i_ < 2; i_++) { \
        int chunk = t + i_ * 256; \
        int row = chunk >> 3, u = chunk & 7; \
        u32 doff = (u32)(row * 128 + ((u ^ (row & 7)) << 4)); \
        int soff = row * 512 + kbyte + u * 16; \
        cpa16(dB +         doff, (sAh) + soff); \
        cpa16(dB +  8192 + doff, (sAl) + soff); \
        cpa16(dB + 16384 + doff, (sBh) + soff); \
        cpa16(dB + 24576 + doff, (sBl) + soff); \
    } \
} while (0)

#define GEMM_COMPUTE(st) do { \
    u32 stB = base + (st) * GSTAGE; \
    u32 AhB = stB, AlB = stB + 8192, BhB = stB + 16384, BlB = stB + 24576; \
    _Pragma("unroll") \
    for (int k16 = 0; k16 < 4; k16++) { \
        u32 adA = (u32)(rowA * 128 + (((k16 * 2 + uA) ^ la7) << 4)); \
        u32 ah[4], al[4]; \
        ldsm4(ah[0], ah[1], ah[2], ah[3], AhB + adA); \
        ldsm4(al[0], al[1], al[2], al[3], AlB + adA); \
        _Pragma("unroll") \
        for (int ntp = 0; ntp < 2; ntp++) { \
            int rowB = cw * 32 + ntp * 16 + rowBb; \
            u32 adB = (u32)(rowB * 128 + (((k16 * 2 + uB) ^ la7) << 4)); \
            u32 b0, b1, b2, b3, c0, c1, c2, c3; \
            ldsm4(b0, b1, b2, b3, BhB + adB); \
            ldsm4(c0, c1, c2, c3, BlB + adB); \
            MMA(acc[2*ntp],     ah, b0, b1); \
            MMA(acc[2*ntp],     ah, c0, c1); \
            MMA(acc[2*ntp],     al, b0, b1); \
            MMA(acc[2*ntp + 1], ah, b2, b3); \
            MMA(acc[2*ntp + 1], ah, c2, c3); \
            MMA(acc[2*ntp + 1], al, b2, b3); \
        } \
    } \
} while (0)

#define GEMM_PRELUDE() \
    const int t = threadIdx.x; \
    const int w = t >> 5, lane = t & 31; \
    const int rw = w & 3, cw = w >> 2; \
    const int gq = lane >> 2, q4 = lane & 3; \
    const int la7 = lane & 7; \
    const int rowA = rw * 16 + la7 + (((lane >> 3) & 1) << 3); \
    const int uA = (lane >> 4) & 1; \
    const int rowBb = la7 + (((lane >> 4) & 1) << 3); \
    const int uB = (lane >> 3) & 1; \
    const u32 base = sptr(dynsmem); \
    float acc[4][4]; \
    _Pragma("unroll") \
    for (int nt_ = 0; nt_ < 4; nt_++) \
        _Pragma("unroll") \
        for (int j_ = 0; j_ < 4; j_++) acc[nt_][j_] = 0.f;

#define GEMM_LOOP(sAh, sAl, sBh, sBl) \
    GEMM_FILL(0, 0, sAh, sAl, sBh, sBl); \
    CP_COMMIT(); \
    for (int kb = 0; kb < 4; kb++) { \
        int st = kb & 1; \
        if (kb < 3) { GEMM_FILL(st ^ 1, (kb + 1) * 64, sAh, sAl, sBh, sBl); CP_COMMIT(); CP_WAIT(1); } \
        else CP_WAIT(0); \
        __syncthreads(); \
        GEMM_COMPUTE(st); \
        __syncthreads(); \
    }

// ---------------------------------------------------------------------------
// QKV projection. Grid (64, 12). Epilogue: Q -> fp16 hi/lo (QSCALE folded),
// K/V -> plain fp16.
// ---------------------------------------------------------------------------
__global__ void __launch_bounds__(256) qkv_mma_kernel()
{
    GEMM_PRELUDE();
    const int m0 = blockIdx.x * 64;
    const int n0 = blockIdx.y * 64;

    const char* sAh = (const char*)(g_Xh + (size_t)m0 * EE);
    const char* sAl = (const char*)(g_Xl + (size_t)m0 * EE);
    const char* sBh = (const char*)(g_Wh + (size_t)n0 * EE);
    const char* sBl = (const char*)(g_Wl + (size_t)n0 * EE);

    GEMM_LOOP(sAh, sAl, sBh, sBl);

    const int mat = n0 >> 8, h = (n0 >> 6) & 3;
    const int r0 = m0 + rw * 16 + gq;
    const int b0_ = r0 >> 11, n2_0 = r0 & 2047;
    const int b1_ = (r0 + 8) >> 11, n2_1 = (r0 + 8) & 2047;

    if (mat == 0) {
        #pragma unroll
        for (int nt = 0; nt < 4; nt++) {
            int c = cw * 32 + nt * 8 + q4 * 2;
            u32 hi, lo;
            split2h(acc[nt][0] * QSCALE, acc[nt][1] * QSCALE, hi, lo);
            size_t a0 = ((size_t)((b0_ * HH + h) * NN + n2_0)) * DKK + c;
            *(u32*)&g_Qh[a0] = hi; *(u32*)&g_Ql[a0] = lo;
            split2h(acc[nt][2] * QSCALE, acc[nt][3] * QSCALE, hi, lo);
            size_t a1 = ((size_t)((b1_ * HH + h) * NN + n2_1)) * DKK + c;
            *(u32*)&g_Qh[a1] = hi; *(u32*)&g_Ql[a1] = lo;
        }
    } else {
        __half* dst = (mat == 1) ? g_K : g_V;
        #pragma unroll
        for (int nt = 0; nt < 4; nt++) {
            int c = cw * 32 + nt * 8 + q4 * 2;
            size_t a0 = ((size_t)((b0_ * HH + h) * NN + n2_0)) * DKK + c;
            *(u32*)&dst[a0] = pack2h(acc[nt][0], acc[nt][1]);
            size_t a1 = ((size_t)((b1_ * HH + h) * NN + n2_1)) * DKK + c;
            *(u32*)&dst[a1] = pack2h(acc[nt][2], acc[nt][3]);
        }
    }
}

// ---------------------------------------------------------------------------
// Output projection. Grid (64, 4). (unchanged)
// ---------------------------------------------------------------------------
__global__ void __launch_bounds__(256) out_mma_kernel(
    const float* __restrict__ bo, float* __restrict__ out)
{
    GEMM_PRELUDE();
    const int m0 = blockIdx.x * 64;
    const int n0 = blockIdx.y * 64;

    const char* sAh = (const char*)(g_Ch + (size_t)m0 * EE);
    const char* sAl = (const char*)(g_Cl + (size_t)m0 * EE);
    const char* sBh = (const char*)(g_Woh + (size_t)n0 * EE);
    const char* sBl = (const char*)(g_Wol + (size_t)n0 * EE);

    GEMM_LOOP(sAh, sAl, sBh, sBl);

    const int r0 = m0 + rw * 16 + gq;
    #pragma unroll
    for (int nt = 0; nt < 4; nt++) {
        int c = n0 + cw * 32 + nt * 8 + q4 * 2;
        float2 bv = *(const float2*)&bo[c];
        float2 v0 = make_float2(acc[nt][0] + bv.x, acc[nt][1] + bv.y);
        float2 v1 = make_float2(acc[nt][2] + bv.x, acc[nt][3] + bv.y);
        *(float2*)&out[(size_t)(r0    ) * EE + c] = v0;
        *(float2*)&out[(size_t)(r0 + 8) * EE + c] = v1;
    }
}

// ---------------------------------------------------------------------------
// Flash attention, fp16 formulation:
//   S  = qh·K + ql·K   (Q split fp16 hi/lo; K plain fp16)   -> 16 MMA / tt
//   PV = P_f16 · V_f16 (single term)                        ->  8 MMA / tt
// Split-K warp groups (g = w>>2), per-group double-buffered {K,V}:
// stage 16 KB, group 32 KB, CTA 64 KB -> 2 CTAs/SM.
// ---------------------------------------------------------------------------
#define ASTAGE 16384
#define AGROUP (2*ASTAGE)

__global__ void __launch_bounds__(256, 2) attn_kernel()
{
    const int t = threadIdx.x;
    const int w = t >> 5, lane = t & 31;
    const int g = w >> 2;
    const int wg = w & 3;
    const int tg = t & 127;
    const int gq = lane >> 2, q4 = lane & 3;
    const int q0 = blockIdx.x * 64;
    const int bh = blockIdx.y;
    const int b  = bh >> 2, h = bh & 3;

    const int r0 = q0 + wg * 16 + gq;

    // ---- Q fragments (fp16 hi/lo) ----
    u32 qh[4][4], ql[4][4];
    {
        const __half* Qh = g_Qh + (size_t)bh * NN * DKK;
        const __half* Ql = g_Ql + (size_t)bh * NN * DKK;
        #pragma unroll
        for (int kc = 0; kc < 4; kc++) {
            int c = kc * 16 + q4 * 2;
            qh[kc][0] = *(const u32*)&Qh[(size_t)(r0    ) * DKK + c    ];
            qh[kc][1] = *(const u32*)&Qh[(size_t)(r0 + 8) * DKK + c    ];
            qh[kc][2] = *(const u32*)&Qh[(size_t)(r0    ) * DKK + c + 8];
            qh[kc][3] = *(const u32*)&Qh[(size_t)(r0 + 8) * DKK + c + 8];
            ql[kc][0] = *(const u32*)&Ql[(size_t)(r0    ) * DKK + c    ];
            ql[kc][1] = *(const u32*)&Ql[(size_t)(r0 + 8) * DKK + c    ];
            ql[kc][2] = *(const u32*)&Ql[(size_t)(r0    ) * DKK + c + 8];
            ql[kc][3] = *(const u32*)&Ql[(size_t)(r0 + 8) * DKK + c + 8];
        }
    }

    float o[8][4];
    #pragma unroll
    for (int nt = 0; nt < 8; nt++)
        #pragma unroll
        for (int j = 0; j < 4; j++) o[nt][j] = 0.f;
    float l0 = 0.f, l1 = 0.f;

    const u64* mr0 = (const u64*)g_mask + ((size_t)(b * NN + r0    )) * (NN / 64);
    const u64* mr1 = (const u64*)g_mask + ((size_t)(b * NN + r0 + 8)) * (NN / 64);

    const u32 gB = sptr(dynsmem) + g * AGROUP;

    const int rS  = (lane & 7) + ((lane >> 4) << 3);
    const int ubS = (lane >> 3) & 1;
    u32 swzS[4];
    #pragma unroll
    for (int kc = 0; kc < 4; kc++)
        swzS[kc] = (u32)(rS * 128 + (((kc * 2 + ubS) ^ (rS & 7)) << 4));
    const int rV  = (lane & 7) + (((lane >> 3) & 1) << 3);
    const int ubV = (lane >> 4) & 1;
    u32 swzV[4];
    #pragma unroll
    for (int ntp = 0; ntp < 4; ntp++)
        swzV[ntp] = (u32)(rV * 128 + (((ntp * 2 + ubV) ^ (rV & 7)) << 4));

    const __half* baseK = g_K + (size_t)bh * NN * DKK;
    const __half* baseV = g_V + (size_t)bh * NN * DKK;

    auto fill = [&](int st, int k0) {
        u32 dB = gB + st * ASTAGE;
        const char* sK = (const char*)(baseK + (size_t)k0 * DKK);
        const char* sV = (const char*)(baseV + (size_t)k0 * DKK);
        #pragma unroll
        for (int i = 0; i < 4; i++) {
            int chunk = tg + i * 128;
            int row = chunk >> 3, u = chunk & 7;
            u32 doff = (u32)(row * 128 + ((u ^ (row & 7)) << 4));
            int soff = row * 128 + u * 16;
            cpa16(dB +        doff, sK + soff);
            cpa16(dB + 8192 + doff, sV + soff);
        }
    };

    fill(0, g * 64);
    CP_COMMIT();

    for (int it = 0; it < 16; it++) {
        const int st = it & 1;
        const int k0 = it * 128 + g * 64;

        if (it < 15) {
            fill(st ^ 1, k0 + 128);
            CP_COMMIT();
            CP_WAIT(1);
        } else {
            CP_WAIT(0);
        }
        asm volatile("bar.sync %0, 128;" :: "r"(1 + g) : "memory");

        const u32 stB = gB + st * ASTAGE;
        const u32 KB_ = stB, VB_ = stB + 8192;

        const u64 m0 = mr0[it * 2 + g];
        const u64 m1 = mr1[it * 2 + g];

        #pragma unroll
        for (int tt = 0; tt < 4; tt++) {
            float s0a[4] = {0.f, 0.f, 0.f, 0.f};
            float s1a[4] = {0.f, 0.f, 0.f, 0.f};
            float s0b[4] = {0.f, 0.f, 0.f, 0.f};
            float s1b[4] = {0.f, 0.f, 0.f, 0.f};
            #pragma unroll
            for (int kc = 0; kc < 4; kc++) {
                float* s0 = (kc < 2) ? s0a : s0b;
                float* s1 = (kc < 2) ? s1a : s1b;
                u32 a0, a1, a2, a3;
                u32 ad = (u32)(tt * 2048) + swzS[kc];
                ldsm4(a0, a1, a2, a3, KB_ + ad);
                MMAH(s0, qh[kc], a0, a1);
                MMAH(s0, ql[kc], a0, a1);
                MMAH(s1, qh[kc], a2, a3);
                MMAH(s1, ql[kc], a2, a3);
            }
            float s0[4], s1[4];
            #pragma unroll
            for (int j = 0; j < 4; j++) { s0[j] = s0a[j] + s0b[j]; s1[j] = s1a[j] + s1b[j]; }

            const int pos0 = tt * 16 + q4 * 2;
            float p00 = ((m0 >> pos0)        & 1) ? ex2f(s0[0]) : 0.f;
            float p01 = ((m0 >> (pos0 + 1))  & 1) ? ex2f(s0[1]) : 0.f;
            float p02 = ((m1 >> pos0)        & 1) ? ex2f(s0[2]) : 0.f;
            float p03 = ((m1 >> (pos0 + 1))  & 1) ? ex2f(s0[3]) : 0.f;
            float p10 = ((m0 >> (pos0 + 8))  & 1) ? ex2f(s1[0]) : 0.f;
            float p11 = ((m0 >> (pos0 + 9))  & 1) ? ex2f(s1[1]) : 0.f;
            float p12 = ((m1 >> (pos0 + 8))  & 1) ? ex2f(s1[2]) : 0.f;
            float p13 = ((m1 >> (pos0 + 9))  & 1) ? ex2f(s1[3]) : 0.f;
            l0 += (p00 + p01) + (p10 + p11);
            l1 += (p02 + p03) + (p12 + p13);

            u32 ah[4];
            ah[0] = pack2h(p00, p01);
            ah[1] = pack2h(p02, p03);
            ah[2] = pack2h(p10, p11);
            ah[3] = pack2h(p12, p13);

            #pragma unroll
            for (int ntp = 0; ntp < 4; ntp++) {
                u32 h0, h1, h2, h3;
                u32 ad = (u32)(tt * 2048) + swzV[ntp];
                ldsm4t(h0, h1, h2, h3, VB_ + ad);
                MMAH(o[2*ntp],     ah, h0, h1);
                MMAH(o[2*ntp + 1], ah, h2, h3);
            }
        }
        asm volatile("bar.sync %0, 128;" :: "r"(1 + g) : "memory");
    }

    // ---- combine: group 1 stores partials into its (now free) region ----
    float* xch = (float*)((char*)dynsmem + AGROUP);
    if (g == 1) {
        float* dst = xch + tg * 35;
        #pragma unroll
        for (int nt = 0; nt < 8; nt++)
            #pragma unroll
            for (int j = 0; j < 4; j++) dst[nt * 4 + j] = o[nt][j];
        dst[32] = l0;
        dst[33] = l1;
    }
    __syncthreads();
    if (g == 1) return;

    {
        const float* src = xch + tg * 35;
        #pragma unroll
        for (int nt = 0; nt < 8; nt++)
            #pragma unroll
            for (int j = 0; j < 4; j++) o[nt][j] += src[nt * 4 + j];
        l0 += src[32];
        l1 += src[33];
    }

    l0 += __shfl_xor_sync(0xffffffffu, l0, 1);
    l0 += __shfl_xor_sync(0xffffffffu, l0, 2);
    l1 += __shfl_xor_sync(0xffffffffu, l1, 1);
    l1 += __shfl_xor_sync(0xffffffffu, l1, 2);
    float inv0 = 1.f / l0, inv1 = 1.f / l1;

    #pragma unroll
    for (int nt = 0; nt < 8; nt++) {
        int d = h * DKK + nt * 8 + q4 * 2;
        u32 hi, lo;
        split2(o[nt][0] * inv0, o[nt][1] * inv0, hi, lo);
        size_t a0 = ((size_t)(b * NN) + r0) * EE + d;
        *(u32*)&g_Ch[a0] = hi; *(u32*)&g_Cl[a0] = lo;
        split2(o[nt][2] * inv1, o[nt][3] * inv1, hi, lo);
        size_t a1 = ((size_t)(b * NN) + r0 + 8) * EE + d;
        *(u32*)&g_Ch[a1] = hi; *(u32*)&g_Cl[a1] = lo;
    }
}

// ---------------------------------------------------------------------------
extern "C" void kernel_launch(void* const* d_in, const int* in_sizes, int n_in,
                              void* d_out, int out_size)
{
    const float* X   = (const float*)d_in[0];
    const int*   Adj = (const int*)  d_in[1];
    const float* Wq  = (const float*)d_in[2];
    const float* Wk  = (const float*)d_in[3];
    const float* Wv  = (const float*)d_in[4];
    const float* Wo  = (const float*)d_in[5];
    const float* bo  = (const float*)d_in[6];
    float* out = (float*)d_out;

    cudaFuncSetAttribute(attn_kernel,
        cudaFuncAttributeMaxDynamicSharedMemorySize, 2 * AGROUP);
    cudaFuncSetAttribute(qkv_mma_kernel,
        cudaFuncAttributeMaxDynamicSharedMemorySize, 2 * GSTAGE);
    cudaFuncSetAttribute(out_mma_kernel,
        cudaFuncAttributeMaxDynamicSharedMemorySize, 2 * GSTAGE);

    prep_kernel<<<34816, 256>>>(Adj, X, Wq, Wk, Wv, Wo);
    qkv_mma_kernel<<<dim3(MTOT/64, 12), 256, 2*GSTAGE>>>();
    attn_kernel<<<dim3(NN/64, BB*HH), 256, 2*AGROUP>>>();
    out_mma_kernel<<<dim3(MTOT/64, 4), 256, 2*GSTAGE>>>(bo, out);
}

// round 15
// speedup vs baseline: 1.7728x; 1.1053x over previous
#include <cuda_runtime.h>
#include <cuda_bf16.h>
#include <cuda_fp16.h>
#include <math.h>
#include <stdint.h>
#include <stddef.h>

#define BB 2
#define NN 2048
#define EE 256
#define HH 4
#define DKK 64
#define MTOT (BB*NN)

// 1/sqrt(64) * log2(e): scores produced in log2 domain for ex2-softmax
#define QSCALE 0.1803368801111204f

typedef unsigned int u32;
typedef unsigned long long u64;

__device__ __forceinline__ float ex2f(float x) {
    float r; asm("ex2.approx.f32 %0, %1;" : "=f"(r) : "f"(x)); return r;
}
__device__ __forceinline__ u32 sptr(const void* p) {
    return (u32)__cvta_generic_to_shared(p);
}
__device__ __forceinline__ void ldsm4(u32& r0, u32& r1, u32& r2, u32& r3, u32 a) {
    asm volatile("ldmatrix.sync.aligned.m8n8.x4.shared.b16 {%0,%1,%2,%3}, [%4];"
        : "=r"(r0), "=r"(r1), "=r"(r2), "=r"(r3) : "r"(a));
}
__device__ __forceinline__ void ldsm4t(u32& r0, u32& r1, u32& r2, u32& r3, u32 a) {
    asm volatile("ldmatrix.sync.aligned.m8n8.x4.trans.shared.b16 {%0,%1,%2,%3}, [%4];"
        : "=r"(r0), "=r"(r1), "=r"(r2), "=r"(r3) : "r"(a));
}
__device__ __forceinline__ void cpa16(u32 dst, const void* src) {
    asm volatile("cp.async.cg.shared.global [%0], [%1], 16;" :: "r"(dst), "l"(src));
}
#define CP_COMMIT() asm volatile("cp.async.commit_group;" ::: "memory")
#define CP_WAIT(n)  asm volatile("cp.async.wait_group %0;" :: "n"(n) : "memory")

// Scratch.
__device__ __align__(16) __nv_bfloat16 g_Xh[MTOT*EE],  g_Xl[MTOT*EE];
__device__ __align__(16) __nv_bfloat16 g_Wh[12*DKK*EE], g_Wl[12*DKK*EE];
__device__ __align__(16) __nv_bfloat16 g_Woh[EE*EE],   g_Wol[EE*EE];
__device__ __align__(16) __half g_Q[BB*HH*NN*DKK];
__device__ __align__(16) __half g_K[BB*HH*NN*DKK];
__device__ __align__(16) __half g_V[BB*HH*NN*DKK];
__device__ __align__(16) __nv_bfloat16 g_Ch[MTOT*EE],  g_Cl[MTOT*EE];
__device__ u32 g_mask[BB*NN*NN/32];

// bf16 hi/lo split of a float pair (projections)
__device__ __forceinline__ void split2(float x, float y, u32& hi, u32& lo) {
    asm("cvt.rn.bf16x2.f32 %0, %1, %2;" : "=r"(hi) : "f"(y), "f"(x));
    float hx = __uint_as_float(hi << 16);
    float hy = __uint_as_float(hi & 0xffff0000u);
    float rx = x - hx, ry = y - hy;
    asm("cvt.rn.bf16x2.f32 %0, %1, %2;" : "=r"(lo) : "f"(ry), "f"(rx));
}
// fp16 pack of a float pair
__device__ __forceinline__ u32 pack2h(float x, float y) {
    u32 r; asm("cvt.rn.f16x2.f32 %0, %1, %2;" : "=r"(r) : "f"(y), "f"(x)); return r;
}

#define MMA(d, a, b0_, b1_) asm volatile( \
    "mma.sync.aligned.m16n8k16.row.col.f32.bf16.bf16.f32 " \
    "{%0,%1,%2,%3}, {%4,%5,%6,%7}, {%8,%9}, {%0,%1,%2,%3};" \
    : "+f"(d[0]), "+f"(d[1]), "+f"(d[2]), "+f"(d[3]) \
    : "r"(a[0]), "r"(a[1]), "r"(a[2]), "r"(a[3]), "r"(b0_), "r"(b1_))

#define MMAH(d, a, b0_, b1_) asm volatile( \
    "mma.sync.aligned.m16n8k16.row.col.f32.f16.f16.f32 " \
    "{%0,%1,%2,%3}, {%4,%5,%6,%7}, {%8,%9}, {%0,%1,%2,%3};" \
    : "+f"(d[0]), "+f"(d[1]), "+f"(d[2]), "+f"(d[3]) \
    : "r"(a[0]), "r"(a[1]), "r"(a[2]), "r"(a[3]), "r"(b0_), "r"(b1_))

extern __shared__ __nv_bfloat16 dynsmem[];

// ---------------------------------------------------------------------------
// Merged prep (unchanged).
// ---------------------------------------------------------------------------
__global__ void __launch_bounds__(256) prep_kernel(
    const int* __restrict__ Adj, const float* __restrict__ X,
    const float* __restrict__ Wq, const float* __restrict__ Wk,
    const float* __restrict__ Wv, const float* __restrict__ Wo)
{
    const int bid = blockIdx.x;
    const int t = threadIdx.x;

    if (bid < 32768) {
        int gid  = bid * 256 + t;
        int word = gid >> 5, lane = gid & 31;
        int v = Adj[(size_t)word * 32 + lane];
        u32 m = __ballot_sync(0xffffffffu, v > 0);
        if (lane == 0) g_mask[word] = m;
    } else if (bid < 33792) {
        int i = ((bid - 32768) * 256 + t) * 4;
        float4 v = *(const float4*)&X[i];
        u32 h0, l0, h1, l1;
        split2(v.x, v.y, h0, l0);
        split2(v.z, v.w, h1, l1);
        *(u32*)&g_Xh[i]     = h0; *(u32*)&g_Xh[i + 2] = h1;
        *(u32*)&g_Xl[i]     = l0; *(u32*)&g_Xl[i + 2] = l1;
    } else if (bid < 34560) {
        int idx = (bid - 33792) * 256 + t;
        int mat = idx >> 16;
        int rem = idx & 65535;
        const float* src = (mat == 0) ? Wq : (mat == 1) ? Wk : Wv;
        int h = rem >> 14, d = (rem >> 6) & 255, e = rem & 63;
        float v = src[rem];
        __nv_bfloat16 hi = __float2bfloat16(v);
        size_t dst = (size_t)((mat * HH + h) * DKK + e) * EE + d;
        g_Wh[dst] = hi;
        g_Wl[dst] = __float2bfloat16(v - __bfloat162float(hi));
    } else {
        int idx = (bid - 34560) * 256 + t;
        float v = Wo[idx];
        __nv_bfloat16 hi = __float2bfloat16(v);
        g_Woh[idx] = hi;
        g_Wol[idx] = __float2bfloat16(v - __bfloat162float(hi));
    }
}

// ---------------------------------------------------------------------------
// Shared GEMM mainloop pieces (unchanged from R13).
// ---------------------------------------------------------------------------
#define GSTAGE 32768

#define GEMM_FILL(st, k0, sAh, sAl, sBh, sBl) do { \
    u32 dB = base + (st) * GSTAGE; \
    int kbyte = (k0) * 2; \
    _Pragma("unroll") \
    for (int i_ = 0; i_ < 2; i_++) { \
        int chunk = t + i_ * 256; \
        int row = chunk >> 3, u = chunk & 7; \
        u32 doff = (u32)(row * 128 + ((u ^ (row & 7)) << 4)); \
        int soff = row * 512 + kbyte + u * 16; \
        cpa16(dB +         doff, (sAh) + soff); \
        cpa16(dB +  8192 + doff, (sAl) + soff); \
        cpa16(dB + 16384 + doff, (sBh) + soff); \
        cpa16(dB + 24576 + doff, (sBl) + soff); \
    } \
} while (0)

#define GEMM_COMPUTE(st) do { \
    u32 stB = base + (st) * GSTAGE; \
    u32 AhB = stB, AlB = stB + 8192, BhB = stB + 16384, BlB = stB + 24576; \
    _Pragma("unroll") \
    for (int k16 = 0; k16 < 4; k16++) { \
        u32 adA = (u32)(rowA * 128 + (((k16 * 2 + uA) ^ la7) << 4)); \
        u32 ah[4], al[4]; \
        ldsm4(ah[0], ah[1], ah[2], ah[3], AhB + adA); \
        ldsm4(al[0], al[1], al[2], al[3], AlB + adA); \
        _Pragma("unroll") \
        for (int ntp = 0; ntp < 2; ntp++) { \
            int rowB = cw * 32 + ntp * 16 + rowBb; \
            u32 adB = (u32)(rowB * 128 + (((k16 * 2 + uB) ^ la7) << 4)); \
            u32 b0, b1, b2, b3, c0, c1, c2, c3; \
            ldsm4(b0, b1, b2, b3, BhB + adB); \
            ldsm4(c0, c1, c2, c3, BlB + adB); \
            MMA(acc[2*ntp],     ah, b0, b1); \
            MMA(acc[2*ntp],     ah, c0, c1); \
            MMA(acc[2*ntp],     al, b0, b1); \
            MMA(acc[2*ntp + 1], ah, b2, b3); \
            MMA(acc[2*ntp + 1], ah, c2, c3); \
            MMA(acc[2*ntp + 1], al, b2, b3); \
        } \
    } \
} while (0)

#define GEMM_PRELUDE() \
    const int t = threadIdx.x; \
    const int w = t >> 5, lane = t & 31; \
    const int rw = w & 3, cw = w >> 2; \
    const int gq = lane >> 2, q4 = lane & 3; \
    const int la7 = lane & 7; \
    const int rowA = rw * 16 + la7 + (((lane >> 3) & 1) << 3); \
    const int uA = (lane >> 4) & 1; \
    const int rowBb = la7 + (((lane >> 4) & 1) << 3); \
    const int uB = (lane >> 3) & 1; \
    const u32 base = sptr(dynsmem); \
    float acc[4][4]; \
    _Pragma("unroll") \
    for (int nt_ = 0; nt_ < 4; nt_++) \
        _Pragma("unroll") \
        for (int j_ = 0; j_ < 4; j_++) acc[nt_][j_] = 0.f;

#define GEMM_LOOP(sAh, sAl, sBh, sBl) \
    GEMM_FILL(0, 0, sAh, sAl, sBh, sBl); \
    CP_COMMIT(); \
    for (int kb = 0; kb < 4; kb++) { \
        int st = kb & 1; \
        if (kb < 3) { GEMM_FILL(st ^ 1, (kb + 1) * 64, sAh, sAl, sBh, sBl); CP_COMMIT(); CP_WAIT(1); } \
        else CP_WAIT(0); \
        __syncthreads(); \
        GEMM_COMPUTE(st); \
        __syncthreads(); \
    }

// ---------------------------------------------------------------------------
// QKV projection. Grid (64, 12). Epilogue: Q/K/V -> plain fp16 (QSCALE in Q).
// ---------------------------------------------------------------------------
__global__ void __launch_bounds__(256) qkv_mma_kernel()
{
    GEMM_PRELUDE();
    const int m0 = blockIdx.x * 64;
    const int n0 = blockIdx.y * 64;

    const char* sAh = (const char*)(g_Xh + (size_t)m0 * EE);
    const char* sAl = (const char*)(g_Xl + (size_t)m0 * EE);
    const char* sBh = (const char*)(g_Wh + (size_t)n0 * EE);
    const char* sBl = (const char*)(g_Wl + (size_t)n0 * EE);

    GEMM_LOOP(sAh, sAl, sBh, sBl);

    const int mat = n0 >> 8, h = (n0 >> 6) & 3;
    const int r0 = m0 + rw * 16 + gq;
    const int b0_ = r0 >> 11, n2_0 = r0 & 2047;
    const int b1_ = (r0 + 8) >> 11, n2_1 = (r0 + 8) & 2047;

    __half* dst = (mat == 0) ? g_Q : (mat == 1) ? g_K : g_V;
    const float mult = (mat == 0) ? QSCALE : 1.0f;
    #pragma unroll
    for (int nt = 0; nt < 4; nt++) {
        int c = cw * 32 + nt * 8 + q4 * 2;
        size_t a0 = ((size_t)((b0_ * HH + h) * NN + n2_0)) * DKK + c;
        *(u32*)&dst[a0] = pack2h(acc[nt][0] * mult, acc[nt][1] * mult);
        size_t a1 = ((size_t)((b1_ * HH + h) * NN + n2_1)) * DKK + c;
        *(u32*)&dst[a1] = pack2h(acc[nt][2] * mult, acc[nt][3] * mult);
    }
}

// ---------------------------------------------------------------------------
// Output projection. Grid (64, 4). (unchanged)
// ---------------------------------------------------------------------------
__global__ void __launch_bounds__(256) out_mma_kernel(
    const float* __restrict__ bo, float* __restrict__ out)
{
    GEMM_PRELUDE();
    const int m0 = blockIdx.x * 64;
    const int n0 = blockIdx.y * 64;

    const char* sAh = (const char*)(g_Ch + (size_t)m0 * EE);
    const char* sAl = (const char*)(g_Cl + (size_t)m0 * EE);
    const char* sBh = (const char*)(g_Woh + (size_t)n0 * EE);
    const char* sBl = (const char*)(g_Wol + (size_t)n0 * EE);

    GEMM_LOOP(sAh, sAl, sBh, sBl);

    const int r0 = m0 + rw * 16 + gq;
    #pragma unroll
    for (int nt = 0; nt < 4; nt++) {
        int c = n0 + cw * 32 + nt * 8 + q4 * 2;
        float2 bv = *(const float2*)&bo[c];
        float2 v0 = make_float2(acc[nt][0] + bv.x, acc[nt][1] + bv.y);
        float2 v1 = make_float2(acc[nt][2] + bv.x, acc[nt][3] + bv.y);
        *(float2*)&out[(size_t)(r0    ) * EE + c] = v0;
        *(float2*)&out[(size_t)(r0 + 8) * EE + c] = v1;
    }
}

// ---------------------------------------------------------------------------
// Flash attention, single-term fp16, triple-buffered, one barrier per tile.
// FIX vs R14: post-loop group barrier before the xch write — at it=15 the
// compute stage is stage 0, which IS the xch region for group 1; without the
// barrier a fast warp overwrote it while slow warps still read it (NaN race).
// ---------------------------------------------------------------------------
#define ASTAGE 16384
#define AGROUP (3*ASTAGE)

__global__ void __launch_bounds__(256, 2) attn_kernel()
{
    const int t = threadIdx.x;
    const int w = t >> 5, lane = t & 31;
    const int g = w >> 2;
    const int wg = w & 3;
    const int tg = t & 127;
    const int gq = lane >> 2, q4 = lane & 3;
    const int q0 = blockIdx.x * 64;
    const int bh = blockIdx.y;
    const int b  = bh >> 2, h = bh & 3;

    const int r0 = q0 + wg * 16 + gq;

    // ---- Q fragments (plain fp16) ----
    u32 qh[4][4];
    {
        const __half* Qp = g_Q + (size_t)bh * NN * DKK;
        #pragma unroll
        for (int kc = 0; kc < 4; kc++) {
            int c = kc * 16 + q4 * 2;
            qh[kc][0] = *(const u32*)&Qp[(size_t)(r0    ) * DKK + c    ];
            qh[kc][1] = *(const u32*)&Qp[(size_t)(r0 + 8) * DKK + c    ];
            qh[kc][2] = *(const u32*)&Qp[(size_t)(r0    ) * DKK + c + 8];
            qh[kc][3] = *(const u32*)&Qp[(size_t)(r0 + 8) * DKK + c + 8];
        }
    }

    float o[8][4];
    #pragma unroll
    for (int nt = 0; nt < 8; nt++)
        #pragma unroll
        for (int j = 0; j < 4; j++) o[nt][j] = 0.f;
    float l0 = 0.f, l1 = 0.f;

    const u64* mr0 = (const u64*)g_mask + ((size_t)(b * NN + r0    )) * (NN / 64);
    const u64* mr1 = (const u64*)g_mask + ((size_t)(b * NN + r0 + 8)) * (NN / 64);

    const u32 gB = sptr(dynsmem) + g * AGROUP;

    const int rS  = (lane & 7) + ((lane >> 4) << 3);
    const int ubS = (lane >> 3) & 1;
    u32 swzS[4];
    #pragma unroll
    for (int kc = 0; kc < 4; kc++)
        swzS[kc] = (u32)(rS * 128 + (((kc * 2 + ubS) ^ (rS & 7)) << 4));
    const int rV  = (lane & 7) + (((lane >> 3) & 1) << 3);
    const int ubV = (lane >> 4) & 1;
    u32 swzV[4];
    #pragma unroll
    for (int ntp = 0; ntp < 4; ntp++)
        swzV[ntp] = (u32)(rV * 128 + (((ntp * 2 + ubV) ^ (rV & 7)) << 4));

    const __half* baseK = g_K + (size_t)bh * NN * DKK;
    const __half* baseV = g_V + (size_t)bh * NN * DKK;

    auto fill = [&](int st_, int k0_) {
        u32 dB = gB + st_ * ASTAGE;
        const char* sK = (const char*)(baseK + (size_t)k0_ * DKK);
        const char* sV = (const char*)(baseV + (size_t)k0_ * DKK);
        #pragma unroll
        for (int i = 0; i < 4; i++) {
            int chunk = tg + i * 128;
            int row = chunk >> 3, u = chunk & 7;
            u32 doff = (u32)(row * 128 + ((u ^ (row & 7)) << 4));
            int soff = row * 128 + u * 16;
            cpa16(dB +        doff, sK + soff);
            cpa16(dB + 8192 + doff, sV + soff);
        }
    };

    fill(0, g * 64);
    CP_COMMIT();
    fill(1, 128 + g * 64);
    CP_COMMIT();

    int st = 0;
    for (int it = 0; it < 16; it++) {
        const int k0 = it * 128 + g * 64;

        if (it < 15) CP_WAIT(1); else CP_WAIT(0);
        asm volatile("bar.sync %0, 128;" :: "r"(1 + g) : "memory");
        if (it < 14) {
            int st2 = st + 2; if (st2 >= 3) st2 -= 3;
            fill(st2, k0 + 256);
            CP_COMMIT();
        }

        const u32 stB = gB + st * ASTAGE;
        const u32 KB_ = stB, VB_ = stB + 8192;

        const u64 m0 = mr0[it * 2 + g];
        const u64 m1 = mr1[it * 2 + g];

        #pragma unroll
        for (int tt = 0; tt < 4; tt++) {
            float s0a[4] = {0.f, 0.f, 0.f, 0.f};
            float s1a[4] = {0.f, 0.f, 0.f, 0.f};
            float s0b[4] = {0.f, 0.f, 0.f, 0.f};
            float s1b[4] = {0.f, 0.f, 0.f, 0.f};
            #pragma unroll
            for (int kc = 0; kc < 4; kc++) {
                float* s0 = (kc < 2) ? s0a : s0b;
                float* s1 = (kc < 2) ? s1a : s1b;
                u32 a0, a1, a2, a3;
                u32 ad = (u32)(tt * 2048) + swzS[kc];
                ldsm4(a0, a1, a2, a3, KB_ + ad);
                MMAH(s0, qh[kc], a0, a1);
                MMAH(s1, qh[kc], a2, a3);
            }
            float s0[4], s1[4];
            #pragma unroll
            for (int j = 0; j < 4; j++) { s0[j] = s0a[j] + s0b[j]; s1[j] = s1a[j] + s1b[j]; }

            const int pos0 = tt * 16 + q4 * 2;
            float p00 = ((m0 >> pos0)        & 1) ? ex2f(s0[0]) : 0.f;
            float p01 = ((m0 >> (pos0 + 1))  & 1) ? ex2f(s0[1]) : 0.f;
            float p02 = ((m1 >> pos0)        & 1) ? ex2f(s0[2]) : 0.f;
            float p03 = ((m1 >> (pos0 + 1))  & 1) ? ex2f(s0[3]) : 0.f;
            float p10 = ((m0 >> (pos0 + 8))  & 1) ? ex2f(s1[0]) : 0.f;
            float p11 = ((m0 >> (pos0 + 9))  & 1) ? ex2f(s1[1]) : 0.f;
            float p12 = ((m1 >> (pos0 + 8))  & 1) ? ex2f(s1[2]) : 0.f;
            float p13 = ((m1 >> (pos0 + 9))  & 1) ? ex2f(s1[3]) : 0.f;
            l0 += (p00 + p01) + (p10 + p11);
            l1 += (p02 + p03) + (p12 + p13);

            u32 ah[4];
            ah[0] = pack2h(p00, p01);
            ah[1] = pack2h(p02, p03);
            ah[2] = pack2h(p10, p11);
            ah[3] = pack2h(p12, p13);

            #pragma unroll
            for (int ntp = 0; ntp < 4; ntp++) {
                u32 h0, h1, h2, h3;
                u32 ad = (u32)(tt * 2048) + swzV[ntp];
                ldsm4t(h0, h1, h2, h3, VB_ + ad);
                MMAH(o[2*ntp],     ah, h0, h1);
                MMAH(o[2*ntp + 1], ah, h2, h3);
            }
        }
        if (++st >= 3) st -= 3;
    }

    // FIX: all group warps must finish tile 15 (stage 0 reads) before the
    // xch region (== group 1 stage 0) is overwritten.
    asm volatile("bar.sync %0, 128;" :: "r"(1 + g) : "memory");

    // ---- combine: group 1 stores partials into its (now free) region ----
    float* xch = (float*)((char*)dynsmem + AGROUP);
    if (g == 1) {
        float* dst = xch + tg * 35;
        #pragma unroll
        for (int nt = 0; nt < 8; nt++)
            #pragma unroll
            for (int j = 0; j < 4; j++) dst[nt * 4 + j] = o[nt][j];
        dst[32] = l0;
        dst[33] = l1;
    }
    __syncthreads();
    if (g == 1) return;

    {
        const float* src = xch + tg * 35;
        #pragma unroll
        for (int nt = 0; nt < 8; nt++)
            #pragma unroll
            for (int j = 0; j < 4; j++) o[nt][j] += src[nt * 4 + j];
        l0 += src[32];
        l1 += src[33];
    }

    l0 += __shfl_xor_sync(0xffffffffu, l0, 1);
    l0 += __shfl_xor_sync(0xffffffffu, l0, 2);
    l1 += __shfl_xor_sync(0xffffffffu, l1, 1);
    l1 += __shfl_xor_sync(0xffffffffu, l1, 2);
    float inv0 = 1.f / l0, inv1 = 1.f / l1;

    #pragma unroll
    for (int nt = 0; nt < 8; nt++) {
        int d = h * DKK + nt * 8 + q4 * 2;
        u32 hi, lo;
        split2(o[nt][0] * inv0, o[nt][1] * inv0, hi, lo);
        size_t a0 = ((size_t)(b * NN) + r0) * EE + d;
        *(u32*)&g_Ch[a0] = hi; *(u32*)&g_Cl[a0] = lo;
        split2(o[nt][2] * inv1, o[nt][3] * inv1, hi, lo);
        size_t a1 = ((size_t)(b * NN) + r0 + 8) * EE + d;
        *(u32*)&g_Ch[a1] = hi; *(u32*)&g_Cl[a1] = lo;
    }
}

// ---------------------------------------------------------------------------
extern "C" void kernel_launch(void* const* d_in, const int* in_sizes, int n_in,
                              void* d_out, int out_size)
{
    const float* X   = (const float*)d_in[0];
    const int*   Adj = (const int*)  d_in[1];
    const float* Wq  = (const float*)d_in[2];
    const float* Wk  = (const float*)d_in[3];
    const float* Wv  = (const float*)d_in[4];
    const float* Wo  = (const float*)d_in[5];
    const float* bo  = (const float*)d_in[6];
    float* out = (float*)d_out;

    cudaFuncSetAttribute(attn_kernel,
        cudaFuncAttributeMaxDynamicSharedMemorySize, 2 * AGROUP);
    cudaFuncSetAttribute(qkv_mma_kernel,
        cudaFuncAttributeMaxDynamicSharedMemorySize, 2 * GSTAGE);
    cudaFuncSetAttribute(out_mma_kernel,
        cudaFuncAttributeMaxDynamicSharedMemorySize, 2 * GSTAGE);

    prep_kernel<<<34816, 256>>>(Adj, X, Wq, Wk, Wv, Wo);
    qkv_mma_kernel<<<dim3(MTOT/64, 12), 256, 2*GSTAGE>>>();
    attn_kernel<<<dim3(NN/64, BB*HH), 256, 2*AGROUP>>>();
    out_mma_kernel<<<dim3(MTOT/64, 4), 256, 2*GSTAGE>>>(bo, out);
}

// round 16
// speedup vs baseline: 2.1463x; 1.2107x over previous
#include <cuda_runtime.h>
#include <cuda_bf16.h>
#include <cuda_fp16.h>
#include <math.h>
#include <stdint.h>
#include <stddef.h>

#define BB 2
#define NN 2048
#define EE 256
#define HH 4
#define DKK 64
#define MTOT (BB*NN)

// 1/sqrt(64) * log2(e): scores produced in log2 domain for ex2-softmax
#define QSCALE 0.1803368801111204f

typedef unsigned int u32;
typedef unsigned long long u64;

__device__ __forceinline__ float ex2f(float x) {
    float r; asm("ex2.approx.f32 %0, %1;" : "=f"(r) : "f"(x)); return r;
}
__device__ __forceinline__ u32 sptr(const void* p) {
    return (u32)__cvta_generic_to_shared(p);
}
__device__ __forceinline__ void ldsm4(u32& r0, u32& r1, u32& r2, u32& r3, u32 a) {
    asm volatile("ldmatrix.sync.aligned.m8n8.x4.shared.b16 {%0,%1,%2,%3}, [%4];"
        : "=r"(r0), "=r"(r1), "=r"(r2), "=r"(r3) : "r"(a));
}
__device__ __forceinline__ void ldsm4t(u32& r0, u32& r1, u32& r2, u32& r3, u32 a) {
    asm volatile("ldmatrix.sync.aligned.m8n8.x4.trans.shared.b16 {%0,%1,%2,%3}, [%4];"
        : "=r"(r0), "=r"(r1), "=r"(r2), "=r"(r3) : "r"(a));
}
__device__ __forceinline__ void cpa16(u32 dst, const void* src) {
    asm volatile("cp.async.cg.shared.global [%0], [%1], 16;" :: "r"(dst), "l"(src));
}
#define CP_COMMIT() asm volatile("cp.async.commit_group;" ::: "memory")
#define CP_WAIT(n)  asm volatile("cp.async.wait_group %0;" :: "n"(n) : "memory")

// Scratch: all GEMM operands fp16.
__device__ __align__(16) __half g_Xh[MTOT*EE],  g_Xl[MTOT*EE];   // X split fp16
__device__ __align__(16) __half g_Wt[12*DKK*EE];                  // W transposed fp16
__device__ __align__(16) __half g_Wo16[EE*EE];                    // Wo fp16 (d-contig)
__device__ __align__(16) __half g_Q[BB*HH*NN*DKK];
__device__ __align__(16) __half g_K[BB*HH*NN*DKK];
__device__ __align__(16) __half g_V[BB*HH*NN*DKK];
__device__ __align__(16) __half g_Ch[MTOT*EE], g_Cl[MTOT*EE];     // C split fp16
__device__ u32 g_mask[BB*NN*NN/32];

// fp16 pack of a float pair
__device__ __forceinline__ u32 pack2h(float x, float y) {
    u32 r; asm("cvt.rn.f16x2.f32 %0, %1, %2;" : "=r"(r) : "f"(y), "f"(x)); return r;
}
// fp16 hi/lo split of a float pair
__device__ __forceinline__ void split2h(float x, float y, u32& hi, u32& lo) {
    hi = pack2h(x, y);
    __half2 hh = *(__half2*)&hi;
    float rx = x - __low2float(hh), ry = y - __high2float(hh);
    lo = pack2h(rx, ry);
}

#define MMAH(d, a, b0_, b1_) asm volatile( \
    "mma.sync.aligned.m16n8k16.row.col.f32.f16.f16.f32 " \
    "{%0,%1,%2,%3}, {%4,%5,%6,%7}, {%8,%9}, {%0,%1,%2,%3};" \
    : "+f"(d[0]), "+f"(d[1]), "+f"(d[2]), "+f"(d[3]) \
    : "r"(a[0]), "r"(a[1]), "r"(a[2]), "r"(a[3]), "r"(b0_), "r"(b1_))

extern __shared__ __half dynsmem[];

// ---------------------------------------------------------------------------
// Merged prep. blockIdx ranges:
//   [0, 8192)     mask (int4-vectorized, redux.or nibble assembly)
//   [8192, 9216)  X split fp16 hi/lo
//   [9216, 9984)  Wq/Wk/Wv transpose -> fp16
//   [9984, 10240) Wo -> fp16
// ---------------------------------------------------------------------------
__global__ void __launch_bounds__(256) prep_kernel(
    const int* __restrict__ Adj, const float* __restrict__ X,
    const float* __restrict__ Wq, const float* __restrict__ Wk,
    const float* __restrict__ Wv, const float* __restrict__ Wo)
{
    const int bid = blockIdx.x;
    const int t = threadIdx.x;

    if (bid < 8192) {                        // ---- adjacency bitmask ----
        int gid  = bid * 256 + t;            // handles entries 4*gid..4*gid+3
        int lane = t & 31;
        int4 v = *(const int4*)&Adj[(size_t)gid * 4];
        u32 nib = (v.x > 0 ? 1u : 0u) | (v.y > 0 ? 2u : 0u)
                | (v.z > 0 ? 4u : 0u) | (v.w > 0 ? 8u : 0u);
        u32 grp = lane >> 3;                 // 8 lanes per 32-bit word
        u32 gmask = 0xFFu << (grp * 8);
        u32 word = __reduce_or_sync(gmask, nib << ((lane & 7) * 4));
        if ((lane & 7) == 0) g_mask[gid >> 3] = word;
    } else if (bid < 9216) {                 // ---- X split fp16 ----
        int i = ((bid - 8192) * 256 + t) * 4;
        float4 v = *(const float4*)&X[i];
        u32 h0, l0, h1, l1;
        split2h(v.x, v.y, h0, l0);
        split2h(v.z, v.w, h1, l1);
        *(u32*)&g_Xh[i]     = h0; *(u32*)&g_Xh[i + 2] = h1;
        *(u32*)&g_Xl[i]     = l0; *(u32*)&g_Xl[i + 2] = l1;
    } else if (bid < 9984) {                 // ---- W transpose fp16 ----
        int idx = (bid - 9216) * 256 + t;
        int mat = idx >> 16;
        int rem = idx & 65535;
        const float* src = (mat == 0) ? Wq : (mat == 1) ? Wk : Wv;
        int h = rem >> 14, d = (rem >> 6) & 255, e = rem & 63;
        g_Wt[(size_t)((mat * HH + h) * DKK + e) * EE + d] = __float2half(src[rem]);
    } else {                                 // ---- Wo fp16 ----
        int idx = (bid - 9984) * 256 + t;
        g_Wo16[idx] = __float2half(Wo[idx]);
    }
}

// ---------------------------------------------------------------------------
// Shared GEMM pieces: 64x64 tile, K=256, 256 thr (8 warps, warp = 16r x 32c).
// A 2-term fp16 (hi/lo), B single fp16. Stage: Ah @0, Al @8192, B @16384 =
// 24 KB; double-buffered swizzled smem via cp.async.
// ---------------------------------------------------------------------------
#define GSTAGE 24576

#define GEMM_FILL(st, k0, sAh, sAl, sB) do { \
    u32 dB = base + (st) * GSTAGE; \
    int kbyte = (k0) * 2; \
    _Pragma("unroll") \
    for (int i_ = 0; i_ < 2; i_++) { \
        int chunk = t + i_ * 256; \
        int row = chunk >> 3, u = chunk & 7; \
        u32 doff = (u32)(row * 128 + ((u ^ (row & 7)) << 4)); \
        int soff = row * 512 + kbyte + u * 16; \
        cpa16(dB +         doff, (sAh) + soff); \
        cpa16(dB +  8192 + doff, (sAl) + soff); \
        cpa16(dB + 16384 + doff, (sB)  + soff); \
    } \
} while (0)

#define GEMM_COMPUTE(st) do { \
    u32 stB = base + (st) * GSTAGE; \
    u32 AhB = stB, AlB = stB + 8192, BB_ = stB + 16384; \
    _Pragma("unroll") \
    for (int k16 = 0; k16 < 4; k16++) { \
        u32 adA = (u32)(rowA * 128 + (((k16 * 2 + uA) ^ la7) << 4)); \
        u32 ah[4], al[4]; \
        ldsm4(ah[0], ah[1], ah[2], ah[3], AhB + adA); \
        ldsm4(al[0], al[1], al[2], al[3], AlB + adA); \
        _Pragma("unroll") \
        for (int ntp = 0; ntp < 2; ntp++) { \
            int rowB = cw * 32 + ntp * 16 + rowBb; \
            u32 adB = (u32)(rowB * 128 + (((k16 * 2 + uB) ^ la7) << 4)); \
            u32 b0, b1, b2, b3; \
            ldsm4(b0, b1, b2, b3, BB_ + adB); \
            MMAH(acc[2*ntp],     ah, b0, b1); \
            MMAH(acc[2*ntp],     al, b0, b1); \
            MMAH(acc[2*ntp + 1], ah, b2, b3); \
            MMAH(acc[2*ntp + 1], al, b2, b3); \
        } \
    } \
} while (0)

#define GEMM_PRELUDE() \
    const int t = threadIdx.x; \
    const int w = t >> 5, lane = t & 31; \
    const int rw = w & 3, cw = w >> 2; \
    const int gq = lane >> 2, q4 = lane & 3; \
    const int la7 = lane & 7; \
    const int rowA = rw * 16 + la7 + (((lane >> 3) & 1) << 3); \
    const int uA = (lane >> 4) & 1; \
    const int rowBb = la7 + (((lane >> 4) & 1) << 3); \
    const int uB = (lane >> 3) & 1; \
    const u32 base = sptr(dynsmem); \
    float acc[4][4]; \
    _Pragma("unroll") \
    for (int nt_ = 0; nt_ < 4; nt_++) \
        _Pragma("unroll") \
        for (int j_ = 0; j_ < 4; j_++) acc[nt_][j_] = 0.f;

#define GEMM_LOOP(sAh, sAl, sB) \
    GEMM_FILL(0, 0, sAh, sAl, sB); \
    CP_COMMIT(); \
    for (int kb = 0; kb < 4; kb++) { \
        int st = kb & 1; \
        if (kb < 3) { GEMM_FILL(st ^ 1, (kb + 1) * 64, sAh, sAl, sB); CP_COMMIT(); CP_WAIT(1); } \
        else CP_WAIT(0); \
        __syncthreads(); \
        GEMM_COMPUTE(st); \
        __syncthreads(); \
    }

// ---------------------------------------------------------------------------
// QKV projection. Grid (64, 12). Epilogue: Q/K/V plain fp16 (QSCALE in Q).
// ---------------------------------------------------------------------------
__global__ void __launch_bounds__(256) qkv_mma_kernel()
{
    GEMM_PRELUDE();
    const int m0 = blockIdx.x * 64;
    const int n0 = blockIdx.y * 64;

    const char* sAh = (const char*)(g_Xh + (size_t)m0 * EE);
    const char* sAl = (const char*)(g_Xl + (size_t)m0 * EE);
    const char* sB  = (const char*)(g_Wt + (size_t)n0 * EE);

    GEMM_LOOP(sAh, sAl, sB);

    const int mat = n0 >> 8, h = (n0 >> 6) & 3;
    const int r0 = m0 + rw * 16 + gq;
    const int b0_ = r0 >> 11, n2_0 = r0 & 2047;
    const int b1_ = (r0 + 8) >> 11, n2_1 = (r0 + 8) & 2047;

    __half* dst = (mat == 0) ? g_Q : (mat == 1) ? g_K : g_V;
    const float mult = (mat == 0) ? QSCALE : 1.0f;
    #pragma unroll
    for (int nt = 0; nt < 4; nt++) {
        int c = cw * 32 + nt * 8 + q4 * 2;
        size_t a0 = ((size_t)((b0_ * HH + h) * NN + n2_0)) * DKK + c;
        *(u32*)&dst[a0] = pack2h(acc[nt][0] * mult, acc[nt][1] * mult);
        size_t a1 = ((size_t)((b1_ * HH + h) * NN + n2_1)) * DKK + c;
        *(u32*)&dst[a1] = pack2h(acc[nt][2] * mult, acc[nt][3] * mult);
    }
}

// ---------------------------------------------------------------------------
// Output projection. Grid (64, 4). A = C (fp16 hi/lo), B = Wo fp16.
// ---------------------------------------------------------------------------
__global__ void __launch_bounds__(256) out_mma_kernel(
    const float* __restrict__ bo, float* __restrict__ out)
{
    GEMM_PRELUDE();
    const int m0 = blockIdx.x * 64;
    const int n0 = blockIdx.y * 64;

    const char* sAh = (const char*)(g_Ch + (size_t)m0 * EE);
    const char* sAl = (const char*)(g_Cl + (size_t)m0 * EE);
    const char* sB  = (const char*)(g_Wo16 + (size_t)n0 * EE);

    GEMM_LOOP(sAh, sAl, sB);

    const int r0 = m0 + rw * 16 + gq;
    #pragma unroll
    for (int nt = 0; nt < 4; nt++) {
        int c = n0 + cw * 32 + nt * 8 + q4 * 2;
        float2 bv = *(const float2*)&bo[c];
        float2 v0 = make_float2(acc[nt][0] + bv.x, acc[nt][1] + bv.y);
        float2 v1 = make_float2(acc[nt][2] + bv.x, acc[nt][3] + bv.y);
        *(float2*)&out[(size_t)(r0    ) * EE + c] = v0;
        *(float2*)&out[(size_t)(r0 + 8) * EE + c] = v1;
    }
}

// ---------------------------------------------------------------------------
// Flash attention (proven R15 body): single-term fp16, triple-buffered,
// one barrier per tile + post-loop barrier guarding the xch region.
// Epilogue writes C as fp16 hi/lo for the out projection.
// ---------------------------------------------------------------------------
#define ASTAGE 16384
#define AGROUP (3*ASTAGE)

__global__ void __launch_bounds__(256, 2) attn_kernel()
{
    const int t = threadIdx.x;
    const int w = t >> 5, lane = t & 31;
    const int g = w >> 2;
    const int wg = w & 3;
    const int tg = t & 127;
    const int gq = lane >> 2, q4 = lane & 3;
    const int q0 = blockIdx.x * 64;
    const int bh = blockIdx.y;
    const int b  = bh >> 2, h = bh & 3;

    const int r0 = q0 + wg * 16 + gq;

    // ---- Q fragments (plain fp16) ----
    u32 qh[4][4];
    {
        const __half* Qp = g_Q + (size_t)bh * NN * DKK;
        #pragma unroll
        for (int kc = 0; kc < 4; kc++) {
            int c = kc * 16 + q4 * 2;
            qh[kc][0] = *(const u32*)&Qp[(size_t)(r0    ) * DKK + c    ];
            qh[kc][1] = *(const u32*)&Qp[(size_t)(r0 + 8) * DKK + c    ];
            qh[kc][2] = *(const u32*)&Qp[(size_t)(r0    ) * DKK + c + 8];
            qh[kc][3] = *(const u32*)&Qp[(size_t)(r0 + 8) * DKK + c + 8];
        }
    }

    float o[8][4];
    #pragma unroll
    for (int nt = 0; nt < 8; nt++)
        #pragma unroll
        for (int j = 0; j < 4; j++) o[nt][j] = 0.f;
    float l0 = 0.f, l1 = 0.f;

    const u64* mr0 = (const u64*)g_mask + ((size_t)(b * NN + r0    )) * (NN / 64);
    const u64* mr1 = (const u64*)g_mask + ((size_t)(b * NN + r0 + 8)) * (NN / 64);

    const u32 gB = sptr(dynsmem) + g * AGROUP;

    const int rS  = (lane & 7) + ((lane >> 4) << 3);
    const int ubS = (lane >> 3) & 1;
    u32 swzS[4];
    #pragma unroll
    for (int kc = 0; kc < 4; kc++)
        swzS[kc] = (u32)(rS * 128 + (((kc * 2 + ubS) ^ (rS & 7)) << 4));
    const int rV  = (lane & 7) + (((lane >> 3) & 1) << 3);
    const int ubV = (lane >> 4) & 1;
    u32 swzV[4];
    #pragma unroll
    for (int ntp = 0; ntp < 4; ntp++)
        swzV[ntp] = (u32)(rV * 128 + (((ntp * 2 + ubV) ^ (rV & 7)) << 4));

    const __half* baseK = g_K + (size_t)bh * NN * DKK;
    const __half* baseV = g_V + (size_t)bh * NN * DKK;

    auto fill = [&](int st_, int k0_) {
        u32 dB = gB + st_ * ASTAGE;
        const char* sK = (const char*)(baseK + (size_t)k0_ * DKK);
        const char* sV = (const char*)(baseV + (size_t)k0_ * DKK);
        #pragma unroll
        for (int i = 0; i < 4; i++) {
            int chunk = tg + i * 128;
            int row = chunk >> 3, u = chunk & 7;
            u32 doff = (u32)(row * 128 + ((u ^ (row & 7)) << 4));
            int soff = row * 128 + u * 16;
            cpa16(dB +        doff, sK + soff);
            cpa16(dB + 8192 + doff, sV + soff);
        }
    };

    fill(0, g * 64);
    CP_COMMIT();
    fill(1, 128 + g * 64);
    CP_COMMIT();

    int st = 0;
    for (int it = 0; it < 16; it++) {
        const int k0 = it * 128 + g * 64;

        if (it < 15) CP_WAIT(1); else CP_WAIT(0);
        asm volatile("bar.sync %0, 128;" :: "r"(1 + g) : "memory");
        if (it < 14) {
            int st2 = st + 2; if (st2 >= 3) st2 -= 3;
            fill(st2, k0 + 256);
            CP_COMMIT();
        }

        const u32 stB = gB + st * ASTAGE;
        const u32 KB_ = stB, VB_ = stB + 8192;

        const u64 m0 = mr0[it * 2 + g];
        const u64 m1 = mr1[it * 2 + g];

        #pragma unroll
        for (int tt = 0; tt < 4; tt++) {
            float s0a[4] = {0.f, 0.f, 0.f, 0.f};
            float s1a[4] = {0.f, 0.f, 0.f, 0.f};
            float s0b[4] = {0.f, 0.f, 0.f, 0.f};
            float s1b[4] = {0.f, 0.f, 0.f, 0.f};
            #pragma unroll
            for (int kc = 0; kc < 4; kc++) {
                float* s0 = (kc < 2) ? s0a : s0b;
                float* s1 = (kc < 2) ? s1a : s1b;
                u32 a0, a1, a2, a3;
                u32 ad = (u32)(tt * 2048) + swzS[kc];
                ldsm4(a0, a1, a2, a3, KB_ + ad);
                MMAH(s0, qh[kc], a0, a1);
                MMAH(s1, qh[kc], a2, a3);
            }
            float s0[4], s1[4];
            #pragma unroll
            for (int j = 0; j < 4; j++) { s0[j] = s0a[j] + s0b[j]; s1[j] = s1a[j] + s1b[j]; }

            const int pos0 = tt * 16 + q4 * 2;
            float p00 = ((m0 >> pos0)        & 1) ? ex2f(s0[0]) : 0.f;
            float p01 = ((m0 >> (pos0 + 1))  & 1) ? ex2f(s0[1]) : 0.f;
            float p02 = ((m1 >> pos0)        & 1) ? ex2f(s0[2]) : 0.f;
            float p03 = ((m1 >> (pos0 + 1))  & 1) ? ex2f(s0[3]) : 0.f;
            float p10 = ((m0 >> (pos0 + 8))  & 1) ? ex2f(s1[0]) : 0.f;
            float p11 = ((m0 >> (pos0 + 9))  & 1) ? ex2f(s1[1]) : 0.f;
            float p12 = ((m1 >> (pos0 + 8))  & 1) ? ex2f(s1[2]) : 0.f;
            float p13 = ((m1 >> (pos0 + 9))  & 1) ? ex2f(s1[3]) : 0.f;
            l0 += (p00 + p01) + (p10 + p11);
            l1 += (p02 + p03) + (p12 + p13);

            u32 ah[4];
            ah[0] = pack2h(p00, p01);
            ah[1] = pack2h(p02, p03);
            ah[2] = pack2h(p10, p11);
            ah[3] = pack2h(p12, p13);

            #pragma unroll
            for (int ntp = 0; ntp < 4; ntp++) {
                u32 h0, h1, h2, h3;
                u32 ad = (u32)(tt * 2048) + swzV[ntp];
                ldsm4t(h0, h1, h2, h3, VB_ + ad);
                MMAH(o[2*ntp],     ah, h0, h1);
                MMAH(o[2*ntp + 1], ah, h2, h3);
            }
        }
        if (++st >= 3) st -= 3;
    }

    // all group warps must finish tile 15 (stage 0 reads) before the
    // xch region (== group 1 stage 0) is overwritten.
    asm volatile("bar.sync %0, 128;" :: "r"(1 + g) : "memory");

    // ---- combine: group 1 stores partials into its (now free) region ----
    float* xch = (float*)((char*)dynsmem + AGROUP);
    if (g == 1) {
        float* dst = xch + tg * 35;
        #pragma unroll
        for (int nt = 0; nt < 8; nt++)
            #pragma unroll
            for (int j = 0; j < 4; j++) dst[nt * 4 + j] = o[nt][j];
        dst[32] = l0;
        dst[33] = l1;
    }
    __syncthreads();
    if (g == 1) return;

    {
        const float* src = xch + tg * 35;
        #pragma unroll
        for (int nt = 0; nt < 8; nt++)
            #pragma unroll
            for (int j = 0; j < 4; j++) o[nt][j] += src[nt * 4 + j];
        l0 += src[32];
        l1 += src[33];
    }

    l0 += __shfl_xor_sync(0xffffffffu, l0, 1);
    l0 += __shfl_xor_sync(0xffffffffu, l0, 2);
    l1 += __shfl_xor_sync(0xffffffffu, l1, 1);
    l1 += __shfl_xor_sync(0xffffffffu, l1, 2);
    float inv0 = 1.f / l0, inv1 = 1.f / l1;

    #pragma unroll
    for (int nt = 0; nt < 8; nt++) {
        int d = h * DKK + nt * 8 + q4 * 2;
        u32 hi, lo;
        split2h(o[nt][0] * inv0, o[nt][1] * inv0, hi, lo);
        size_t a0 = ((size_t)(b * NN) + r0) * EE + d;
        *(u32*)&g_Ch[a0] = hi; *(u32*)&g_Cl[a0] = lo;
        split2h(o[nt][2] * inv1, o[nt][3] * inv1, hi, lo);
        size_t a1 = ((size_t)(b * NN) + r0 + 8) * EE + d;
        *(u32*)&g_Ch[a1] = hi; *(u32*)&g_Cl[a1] = lo;
    }
}

// ---------------------------------------------------------------------------
extern "C" void kernel_launch(void* const* d_in, const int* in_sizes, int n_in,
                              void* d_out, int out_size)
{
    const float* X   = (const float*)d_in[0];
    const int*   Adj = (const int*)  d_in[1];
    const float* Wq  = (const float*)d_in[2];
    const float* Wk  = (const float*)d_in[3];
    const float* Wv  = (const float*)d_in[4];
    const float* Wo  = (const float*)d_in[5];
    const float* bo  = (const float*)d_in[6];
    float* out = (float*)d_out;

    cudaFuncSetAttribute(attn_kernel,
        cudaFuncAttributeMaxDynamicSharedMemorySize, 2 * AGROUP);
    cudaFuncSetAttribute(qkv_mma_kernel,
        cudaFuncAttributeMaxDynamicSharedMemorySize, 2 * GSTAGE);
    cudaFuncSetAttribute(out_mma_kernel,
        cudaFuncAttributeMaxDynamicSharedMemorySize, 2 * GSTAGE);

    prep_kernel<<<10240, 256>>>(Adj, X, Wq, Wk, Wv, Wo);
    qkv_mma_kernel<<<dim3(MTOT/64, 12), 256, 2*GSTAGE>>>();
    attn_kernel<<<dim3(NN/64, BB*HH), 256, 2*AGROUP>>>();
    out_mma_kernel<<<dim3(MTOT/64, 4), 256, 2*GSTAGE>>>(bo, out);
}